// round 1
// baseline (speedup 1.0000x reference)
#include <cuda_runtime.h>
#include <math.h>

#define Bb 2
#define Tt 1024
#define Dd 1024
#define Hh 8
#define DEPTH 5
#define DHh 128
#define NTOK (Bb*Tt)

// scratch (device globals: allocation-free per harness rules)
__device__ float g_paths[NTOK*Hh*DEPTH];            // [token, h*5+d]
__device__ float g_v[NTOK*Dd];                      // x @ Wv   [token, h*128+dh]
__device__ float g_attn[(size_t)Bb*Hh*Tt*Tt];       // softmaxed attn, zeros above diagonal
__device__ float g_ctx[NTOK*Dd];                    // ctx in [b,t, h*128+dh] layout

// ---------------------------------------------------------------------------
// paths = sigmoid(x @ Wp + bp): one block per token, 8 warps = 8 heads,
// each warp does 5 depth columns via warp-reduced dot products.
// ---------------------------------------------------------------------------
__global__ __launch_bounds__(256) void paths_kernel(const float* __restrict__ x,
                                                    const float* __restrict__ Wp,
                                                    const float* __restrict__ bp) {
    __shared__ float xs[Dd];
    int tok = blockIdx.x;
    int tid = threadIdx.x;
    const float* xr = x + (size_t)tok * Dd;
    for (int i = tid; i < Dd; i += 256) xs[i] = xr[i];
    __syncthreads();
    int warp = tid >> 5, lane = tid & 31;
    #pragma unroll
    for (int j = 0; j < DEPTH; j++) {
        int col = warp * DEPTH + j;
        float s = 0.f;
        for (int k = lane; k < Dd; k += 32) s += xs[k] * Wp[k * (Hh*DEPTH) + col];
        #pragma unroll
        for (int o = 16; o > 0; o >>= 1) s += __shfl_xor_sync(0xffffffffu, s, o);
        if (lane == 0) {
            float z = s + bp[col];
            g_paths[tok * (Hh*DEPTH) + col] = 1.f / (1.f + expf(-z));
        }
    }
}

// ---------------------------------------------------------------------------
// Classic fp32 SGEMM: C[M,N] = A[M,K] * B[K,N], all row-major.
// BM=BN=128, BK=8, 256 threads, 8x8 per thread. M%128==0, N%128==0, K%8==0.
// ---------------------------------------------------------------------------
__global__ __launch_bounds__(256) void sgemm128(const float* __restrict__ A,
                                                const float* __restrict__ Bw,
                                                float* __restrict__ C,
                                                int M, int N, int K) {
    __shared__ float As[8][128];
    __shared__ float Bs[8][128];
    int tid = threadIdx.x;
    int bm = blockIdx.y * 128, bn = blockIdx.x * 128;
    int tx = tid & 15, ty = tid >> 4;
    float acc[8][8];
    #pragma unroll
    for (int i = 0; i < 8; i++)
        #pragma unroll
        for (int j = 0; j < 8; j++) acc[i][j] = 0.f;

    int arow = tid >> 1;            // 0..127
    int acol = (tid & 1) * 4;       // 0 or 4
    int brow = tid >> 5;            // 0..7
    int bcol = (tid & 31) * 4;      // 0..124
    const float* Aptr = A + (size_t)(bm + arow) * K + acol;
    const float* Bptr = Bw + (size_t)brow * N + bn + bcol;

    for (int k0 = 0; k0 < K; k0 += 8) {
        float4 a4 = *(const float4*)(Aptr + k0);
        float4 b4 = *(const float4*)(Bptr + (size_t)k0 * N);
        As[acol + 0][arow] = a4.x;
        As[acol + 1][arow] = a4.y;
        As[acol + 2][arow] = a4.z;
        As[acol + 3][arow] = a4.w;
        *(float4*)&Bs[brow][bcol] = b4;
        __syncthreads();
        #pragma unroll
        for (int kk = 0; kk < 8; kk++) {
            float a[8], b[8];
            *(float4*)(a)     = *(float4*)&As[kk][ty * 8];
            *(float4*)(a + 4) = *(float4*)&As[kk][ty * 8 + 4];
            *(float4*)(b)     = *(float4*)&Bs[kk][tx * 8];
            *(float4*)(b + 4) = *(float4*)&Bs[kk][tx * 8 + 4];
            #pragma unroll
            for (int i = 0; i < 8; i++)
                #pragma unroll
                for (int j = 0; j < 8; j++) acc[i][j] += a[i] * b[j];
        }
        __syncthreads();
    }
    #pragma unroll
    for (int i = 0; i < 8; i++) {
        float* cp = C + (size_t)(bm + ty * 8 + i) * N + bn + tx * 8;
        *(float4*)(cp)     = make_float4(acc[i][0], acc[i][1], acc[i][2], acc[i][3]);
        *(float4*)(cp + 4) = make_float4(acc[i][4], acc[i][5], acc[i][6], acc[i][7]);
    }
}

// ---------------------------------------------------------------------------
// p-adic similarity + causal softmax. One block per (b,h,q) row; 256 threads,
// each owns 4 k positions. sim in (0,1] so exp is stable without max-shift.
// Writes a dense row (zeros for k>q) so attn@V can be a dense GEMM.
// ---------------------------------------------------------------------------
__global__ __launch_bounds__(256) void attn_kernel(const float* __restrict__ paths,
                                                   float* __restrict__ attn) {
    int q = blockIdx.x, h = blockIdx.y, b = blockIdx.z;
    int tid = threadIdx.x;
    __shared__ float pqs[DEPTH];
    __shared__ float wsum[8];
    __shared__ float total;
    if (tid < DEPTH) pqs[tid] = paths[((size_t)(b*Tt + q) * Hh + h) * DEPTH + tid];
    __syncthreads();
    float p0 = pqs[0], p1 = pqs[1], p2 = pqs[2], p3 = pqs[3], p4 = pqs[4];

    float e[4];
    float sum = 0.f;
    #pragma unroll
    for (int i = 0; i < 4; i++) {
        int k = tid + i * 256;
        float ev = 0.f;
        if (k <= q) {
            const float* pk = paths + ((size_t)(b*Tt + k) * Hh + h) * DEPTH;
            float k0 = pk[0], k1 = pk[1], k2 = pk[2], k3 = pk[3], k4 = pk[4];
            float prod = p0*k0 + (1.f-p0)*(1.f-k0);
            float s = prod;
            prod *= p1*k1 + (1.f-p1)*(1.f-k1); s += prod;
            prod *= p2*k2 + (1.f-p2)*(1.f-k2); s += prod;
            prod *= p3*k3 + (1.f-p3)*(1.f-k3); s += prod;
            prod *= p4*k4 + (1.f-p4)*(1.f-k4); s += prod;
            ev = expf(s * (1.0f / DEPTH));
        }
        e[i] = ev;
        sum += ev;
    }
    #pragma unroll
    for (int o = 16; o > 0; o >>= 1) sum += __shfl_xor_sync(0xffffffffu, sum, o);
    if ((tid & 31) == 0) wsum[tid >> 5] = sum;
    __syncthreads();
    if (tid == 0) {
        float t = 0.f;
        #pragma unroll
        for (int w = 0; w < 8; w++) t += wsum[w];
        total = t;
    }
    __syncthreads();
    float inv = 1.f / total;
    float* row = attn + ((size_t)((b*Hh + h) * Tt) + q) * Tt;
    #pragma unroll
    for (int i = 0; i < 4; i++) row[tid + i * 256] = e[i] * inv;
}

// ---------------------------------------------------------------------------
// ctx = attn @ V, batched over (b,h), causal K-clipping per q-tile.
// BM=64 (q), BN=128 (=DH), BK=16, 256 threads, 4x8 per thread.
// V is read directly from the x@Wv result (head slice), and the store fuses
// the (b,h,t,d)->(b,t,h*128+d) transpose.
// ---------------------------------------------------------------------------
__global__ __launch_bounds__(256) void av_kernel(const float* __restrict__ attn,
                                                 const float* __restrict__ v,
                                                 float* __restrict__ ctx) {
    int qt = blockIdx.x, h = blockIdx.y, b = blockIdx.z;
    __shared__ float As[16][65];
    __shared__ float Bs[16][128];
    int tid = threadIdx.x;
    int tx = tid & 15, ty = tid >> 4;
    float acc[4][8];
    #pragma unroll
    for (int i = 0; i < 4; i++)
        #pragma unroll
        for (int j = 0; j < 8; j++) acc[i][j] = 0.f;

    const float* Abase = attn + ((size_t)((b*Hh + h) * Tt) + qt * 64) * Tt;
    int arow = tid >> 2, acol = (tid & 3) * 4;
    int br = tid >> 5,  bc = (tid & 31) * 4;
    int K = qt * 64 + 64;   // causal: rows in this tile never attend beyond here

    for (int k0 = 0; k0 < K; k0 += 16) {
        float4 a4 = *(const float4*)(Abase + (size_t)arow * Tt + k0 + acol);
        As[acol + 0][arow] = a4.x;
        As[acol + 1][arow] = a4.y;
        As[acol + 2][arow] = a4.z;
        As[acol + 3][arow] = a4.w;
        const float* vb = v + (size_t)(b*Tt + k0) * Dd + h * DHh;
        *(float4*)&Bs[br][bc]     = *(const float4*)(vb + (size_t)br * Dd + bc);
        *(float4*)&Bs[br + 8][bc] = *(const float4*)(vb + (size_t)(br + 8) * Dd + bc);
        __syncthreads();
        #pragma unroll
        for (int kk = 0; kk < 16; kk++) {
            float a0 = As[kk][ty*4+0], a1 = As[kk][ty*4+1];
            float a2 = As[kk][ty*4+2], a3 = As[kk][ty*4+3];
            float bfr[8];
            *(float4*)(bfr)     = *(float4*)&Bs[kk][tx * 8];
            *(float4*)(bfr + 4) = *(float4*)&Bs[kk][tx * 8 + 4];
            #pragma unroll
            for (int j = 0; j < 8; j++) {
                acc[0][j] += a0 * bfr[j];
                acc[1][j] += a1 * bfr[j];
                acc[2][j] += a2 * bfr[j];
                acc[3][j] += a3 * bfr[j];
            }
        }
        __syncthreads();
    }
    #pragma unroll
    for (int i = 0; i < 4; i++) {
        int q = qt * 64 + ty * 4 + i;
        float* cp = ctx + (size_t)(b*Tt + q) * Dd + h * DHh + tx * 8;
        *(float4*)(cp)     = make_float4(acc[i][0], acc[i][1], acc[i][2], acc[i][3]);
        *(float4*)(cp + 4) = make_float4(acc[i][4], acc[i][5], acc[i][6], acc[i][7]);
    }
}

extern "C" void kernel_launch(void* const* d_in, const int* in_sizes, int n_in,
                              void* d_out, int out_size) {
    const float* x  = (const float*)d_in[0];
    const float* Wp = (const float*)d_in[1];
    const float* bp = (const float*)d_in[2];
    const float* Wv = (const float*)d_in[3];
    const float* Wo = (const float*)d_in[4];
    float* out = (float*)d_out;

    float *paths, *v, *attn, *ctx;
    cudaGetSymbolAddress((void**)&paths, g_paths);
    cudaGetSymbolAddress((void**)&v,     g_v);
    cudaGetSymbolAddress((void**)&attn,  g_attn);
    cudaGetSymbolAddress((void**)&ctx,   g_ctx);

    paths_kernel<<<NTOK, 256>>>(x, Wp, bp);
    sgemm128<<<dim3(Dd/128, NTOK/128), 256>>>(x, Wv, v, NTOK, Dd, Dd);
    attn_kernel<<<dim3(Tt, Hh, Bb), 256>>>(paths, attn);
    av_kernel<<<dim3(Tt/64, Hh, Bb), 256>>>(attn, v, ctx);
    sgemm128<<<dim3(Dd/128, NTOK/128), 256>>>(ctx, Wo, out, NTOK, Dd, Dd);
}

// round 2
// speedup vs baseline: 2.0613x; 2.0613x over previous
#include <cuda_runtime.h>
#include <math.h>
#include <stdint.h>

#define Bb 2
#define Tt 1024
#define Dd 1024
#define Hh 8
#define DEPTH 5
#define DHh 128
#define NTOK (Bb*Tt)

// scratch (device globals: allocation-free per harness rules)
__device__ float g_paths[NTOK*Hh*DEPTH];            // [token, h*5+d]
__device__ float g_v[NTOK*Dd];                      // x @ Wv   [token, h*128+dh]
__device__ float g_attn[(size_t)Bb*Hh*Tt*Tt];       // softmaxed attn (zeros above diag)
__device__ float g_ctx[NTOK*Dd];                    // ctx in [b,t, h*128+dh] layout

__device__ __forceinline__ uint32_t f2tf(float f) {
    uint32_t r; asm("cvt.rna.tf32.f32 %0, %1;" : "=r"(r) : "f"(f)); return r;
}

__device__ __forceinline__ void mma_tf32(float c[4],
                                         uint32_t a0, uint32_t a1, uint32_t a2, uint32_t a3,
                                         uint32_t b0, uint32_t b1) {
    asm volatile("mma.sync.aligned.m16n8k8.row.col.f32.tf32.tf32.f32 "
                 "{%0,%1,%2,%3}, {%4,%5,%6,%7}, {%8,%9}, {%0,%1,%2,%3};"
                 : "+f"(c[0]), "+f"(c[1]), "+f"(c[2]), "+f"(c[3])
                 : "r"(a0), "r"(a1), "r"(a2), "r"(a3), "r"(b0), "r"(b1));
}

// ---------------------------------------------------------------------------
// tf32 tensor-core GEMM core: C[128,128] tile of A[M,K]*B[K,N], row-major.
// 256 threads = 8 warps (2x4), warp tile 64x32, mma m16n8k8, BK=32.
// Requires K % 32 == 0, tiles fully in-bounds.
// ---------------------------------------------------------------------------
__device__ __forceinline__ void gemm128_tf32_core(
    const float* __restrict__ A, int lda,
    const float* __restrict__ B, int ldb,
    float* __restrict__ C, int ldc,
    int K, int bm, int bn)
{
    __shared__ float As[128][40];   // [m][k] pad->conflict-light frags, aligned STS.128
    __shared__ float Bs[32][136];   // [k][n] conflict-free frags + STS.128

    int tid = threadIdx.x;
    int warp = tid >> 5, lane = tid & 31;
    int wm = (warp & 1) * 64;       // warp grid: 2 (m) x 4 (n)
    int wn = (warp >> 1) * 32;
    int tg = lane >> 2;             // 0..7
    int tk = lane & 3;              // 0..3

    float acc[4][4][4];
    #pragma unroll
    for (int mt = 0; mt < 4; mt++)
        #pragma unroll
        for (int nt = 0; nt < 4; nt++)
            #pragma unroll
            for (int i = 0; i < 4; i++) acc[mt][nt][i] = 0.f;

    int am = tid >> 3;              // 0..31 (+32p)
    int ak = (tid & 7) * 4;
    int bkr = tid >> 5;             // 0..7 (+8p)
    int bn4 = lane * 4;

    for (int k0 = 0; k0 < K; k0 += 32) {
        float4 ar[4], br[4];
        #pragma unroll
        for (int p = 0; p < 4; p++)
            ar[p] = *(const float4*)(A + (size_t)(bm + am + 32*p) * lda + k0 + ak);
        #pragma unroll
        for (int p = 0; p < 4; p++)
            br[p] = *(const float4*)(B + (size_t)(k0 + bkr + 8*p) * ldb + bn + bn4);

        __syncthreads();
        #pragma unroll
        for (int p = 0; p < 4; p++) {
            uint4 t4 = make_uint4(f2tf(ar[p].x), f2tf(ar[p].y), f2tf(ar[p].z), f2tf(ar[p].w));
            *(uint4*)&As[am + 32*p][ak] = t4;
        }
        #pragma unroll
        for (int p = 0; p < 4; p++) {
            uint4 t4 = make_uint4(f2tf(br[p].x), f2tf(br[p].y), f2tf(br[p].z), f2tf(br[p].w));
            *(uint4*)&Bs[bkr + 8*p][bn4] = t4;
        }
        __syncthreads();

        #pragma unroll
        for (int kq = 0; kq < 32; kq += 8) {
            uint32_t af[4][4], bf[4][2];
            #pragma unroll
            for (int mt = 0; mt < 4; mt++) {
                int m = wm + mt * 16 + tg;
                af[mt][0] = __float_as_uint(As[m][kq + tk]);
                af[mt][1] = __float_as_uint(As[m + 8][kq + tk]);
                af[mt][2] = __float_as_uint(As[m][kq + tk + 4]);
                af[mt][3] = __float_as_uint(As[m + 8][kq + tk + 4]);
            }
            #pragma unroll
            for (int nt = 0; nt < 4; nt++) {
                int n = wn + nt * 8 + tg;
                bf[nt][0] = __float_as_uint(Bs[kq + tk][n]);
                bf[nt][1] = __float_as_uint(Bs[kq + tk + 4][n]);
            }
            #pragma unroll
            for (int mt = 0; mt < 4; mt++)
                #pragma unroll
                for (int nt = 0; nt < 4; nt++)
                    mma_tf32(acc[mt][nt], af[mt][0], af[mt][1], af[mt][2], af[mt][3],
                             bf[nt][0], bf[nt][1]);
        }
    }

    #pragma unroll
    for (int mt = 0; mt < 4; mt++) {
        #pragma unroll
        for (int nt = 0; nt < 4; nt++) {
            int r0 = bm + wm + mt * 16 + tg;
            int cc = bn + wn + nt * 8 + tk * 2;
            *(float2*)&C[(size_t)r0 * ldc + cc]       = make_float2(acc[mt][nt][0], acc[mt][nt][1]);
            *(float2*)&C[(size_t)(r0 + 8) * ldc + cc] = make_float2(acc[mt][nt][2], acc[mt][nt][3]);
        }
    }
}

// dense GEMM wrapper: grid.x = N/128, grid.y = M/128
__global__ __launch_bounds__(256) void gemm_tf32_kernel(const float* __restrict__ A,
                                                        const float* __restrict__ Bw,
                                                        float* __restrict__ C,
                                                        int K, int N) {
    gemm128_tf32_core(A, K, Bw, N, C, N, K, blockIdx.y * 128, blockIdx.x * 128);
}

// attn@V wrapper, batched over (b,h), causal K clipping. grid = (T/128, B*H)
__global__ __launch_bounds__(256) void av_tf32_kernel(const float* __restrict__ attn,
                                                      const float* __restrict__ v,
                                                      float* __restrict__ ctx) {
    int qt = blockIdx.x, bh = blockIdx.y;
    int b = bh >> 3, h = bh & 7;
    const float* A  = attn + (size_t)bh * Tt * Tt;
    const float* Bv = v    + (size_t)b * Tt * Dd + h * DHh;
    float*       C  = ctx  + (size_t)b * Tt * Dd + h * DHh;
    gemm128_tf32_core(A, Tt, Bv, Dd, C, Dd, (qt + 1) * 128, qt * 128, 0);
}

// ---------------------------------------------------------------------------
// paths = sigmoid(x @ Wp + bp): one block per token, 8 warps = 8 heads.
// ---------------------------------------------------------------------------
__global__ __launch_bounds__(256) void paths_kernel(const float* __restrict__ x,
                                                    const float* __restrict__ Wp,
                                                    const float* __restrict__ bp) {
    __shared__ float xs[Dd];
    int tok = blockIdx.x;
    int tid = threadIdx.x;
    const float* xr = x + (size_t)tok * Dd;
    for (int i = tid; i < Dd; i += 256) xs[i] = xr[i];
    __syncthreads();
    int warp = tid >> 5, lane = tid & 31;
    #pragma unroll
    for (int j = 0; j < DEPTH; j++) {
        int col = warp * DEPTH + j;
        float s = 0.f;
        for (int k = lane; k < Dd; k += 32) s += xs[k] * Wp[k * (Hh*DEPTH) + col];
        #pragma unroll
        for (int o = 16; o > 0; o >>= 1) s += __shfl_xor_sync(0xffffffffu, s, o);
        if (lane == 0) {
            float z = s + bp[col];
            g_paths[tok * (Hh*DEPTH) + col] = 1.f / (1.f + expf(-z));
        }
    }
}

// ---------------------------------------------------------------------------
// p-adic sim + causal softmax, smem-staged paths table.
// Block = (qt of 64 q-rows, h, b); 8 warps x 8 rows each; per-lane 32-reg
// exp buffer; full dense row written (zeros above diag).
// ---------------------------------------------------------------------------
__global__ __launch_bounds__(256) void attn2_kernel(const float* __restrict__ paths,
                                                    float* __restrict__ attn) {
    __shared__ float pks[Tt * DEPTH];   // 20KB max
    int qt = blockIdx.x, h = blockIdx.y, b = blockIdx.z;
    int tid = threadIdx.x;
    int kmax = (qt + 1) * 64;
    const float* pb = paths + (size_t)b * Tt * (Hh*DEPTH) + h * DEPTH;
    for (int idx = tid; idx < kmax * DEPTH; idx += 256) {
        int k = idx / DEPTH, d = idx - k * DEPTH;
        pks[idx] = pb[(size_t)k * (Hh*DEPTH) + d];
    }
    __syncthreads();

    int warp = tid >> 5, lane = tid & 31;
    float* abase = attn + (size_t)((b * Hh + h) * Tt) * Tt;

    for (int r = 0; r < 8; r++) {
        int q = qt * 64 + r * 8 + warp;
        float p0 = pks[q*5+0], p1 = pks[q*5+1], p2 = pks[q*5+2],
              p3 = pks[q*5+3], p4 = pks[q*5+4];
        float o0 = 1.f - p0, o1 = 1.f - p1, o2 = 1.f - p2, o3 = 1.f - p3, o4 = 1.f - p4;

        float e[32];
        float sum = 0.f;
        #pragma unroll
        for (int i = 0; i < 32; i++) {
            int k = lane + i * 32;
            float ev = 0.f;
            if (k <= q) {
                float k0 = pks[k*5+0], k1 = pks[k*5+1], k2 = pks[k*5+2],
                      k3 = pks[k*5+3], k4 = pks[k*5+4];
                float prod = p0 * k0 + o0 * (1.f - k0);
                float s = prod;
                prod *= p1 * k1 + o1 * (1.f - k1); s += prod;
                prod *= p2 * k2 + o2 * (1.f - k2); s += prod;
                prod *= p3 * k3 + o3 * (1.f - k3); s += prod;
                prod *= p4 * k4 + o4 * (1.f - k4); s += prod;
                ev = __expf(s * (1.0f / DEPTH));
            }
            e[i] = ev;
            sum += ev;
        }
        #pragma unroll
        for (int o = 16; o > 0; o >>= 1) sum += __shfl_xor_sync(0xffffffffu, sum, o);
        float inv = 1.f / sum;
        float* row = abase + (size_t)q * Tt;
        #pragma unroll
        for (int i = 0; i < 32; i++) row[lane + i * 32] = e[i] * inv;
    }
}

extern "C" void kernel_launch(void* const* d_in, const int* in_sizes, int n_in,
                              void* d_out, int out_size) {
    const float* x  = (const float*)d_in[0];
    const float* Wp = (const float*)d_in[1];
    const float* bp = (const float*)d_in[2];
    const float* Wv = (const float*)d_in[3];
    const float* Wo = (const float*)d_in[4];
    float* out = (float*)d_out;

    float *paths, *v, *attn, *ctx;
    cudaGetSymbolAddress((void**)&paths, g_paths);
    cudaGetSymbolAddress((void**)&v,     g_v);
    cudaGetSymbolAddress((void**)&attn,  g_attn);
    cudaGetSymbolAddress((void**)&ctx,   g_ctx);

    paths_kernel<<<NTOK, 256>>>(x, Wp, bp);
    gemm_tf32_kernel<<<dim3(Dd/128, NTOK/128), 256>>>(x, Wv, v, Dd, Dd);
    attn2_kernel<<<dim3(Tt/64, Hh, Bb), 256>>>(paths, attn);
    av_tf32_kernel<<<dim3(Tt/128, Bb*Hh), 256>>>(attn, v, ctx);
    gemm_tf32_kernel<<<dim3(Dd/128, NTOK/128), 256>>>(ctx, Wo, out, Dd, Dd);
}

// round 4
// speedup vs baseline: 2.2361x; 1.0848x over previous
#include <cuda_runtime.h>
#include <math.h>
#include <stdint.h>

#define Bb 2
#define Tt 1024
#define Dd 1024
#define Hh 8
#define DEPTH 5
#define NTOK (Bb*Tt)

// ---------------- scratch (device globals; allocation-free) ----------------
__device__ float g_paths[NTOK*Hh*DEPTH];      // [token][h*5+d]
__device__ float g_xr[NTOK*Dd];               // tf32(rna)-rounded x
__device__ float g_wvr[Dd*Dd];                // rounded Wv  [k][n]
__device__ float g_wor[Dd*Dd];                // rounded Wo  [k][n]
__device__ float g_v[NTOK*Dd];                // V = x@Wv, rounded, [b*T+t][h*128+dh]
__device__ float g_attn[(size_t)Bb*Hh*Tt*Tt]; // attn rows (rounded; valid to causal 128-boundary)
__device__ float g_ctx[NTOK*Dd];              // ctx, rounded

// ---------------- helpers ----------------
__device__ __forceinline__ float rnaf(float f) {
    uint32_t r; asm("cvt.rna.tf32.f32 %0, %1;" : "=r"(r) : "f"(f));
    return __uint_as_float(r);
}
__device__ __forceinline__ uint32_t smem_u32(const void* p) {
    uint32_t a;
    asm("{ .reg .u64 t; cvta.to.shared.u64 t, %1; cvt.u32.u64 %0, t; }" : "=r"(a) : "l"(p));
    return a;
}
__device__ __forceinline__ void cp16(uint32_t dst, const void* src) {
    asm volatile("cp.async.cg.shared.global [%0], [%1], 16;" :: "r"(dst), "l"(src));
}
__device__ __forceinline__ void mma_tf32(float c[4],
                                         uint32_t a0, uint32_t a1, uint32_t a2, uint32_t a3,
                                         uint32_t b0, uint32_t b1) {
    asm volatile("mma.sync.aligned.m16n8k8.row.col.f32.tf32.tf32.f32 "
                 "{%0,%1,%2,%3}, {%4,%5,%6,%7}, {%8,%9}, {%0,%1,%2,%3};"
                 : "+f"(c[0]), "+f"(c[1]), "+f"(c[2]), "+f"(c[3])
                 : "r"(a0), "r"(a1), "r"(a2), "r"(a3), "r"(b0), "r"(b1));
}

// ---------------------------------------------------------------------------
// mma.sync tf32 GEMM core: C[64,128] tile of A[M,K] * B[K,N], row-major.
// 256 threads = 8 warps (2m x 4n), warp tile 32x32. BK=32.
// 3-stage cp.async pipeline. Smem pads: A stride 36, B stride 136 (both
// conflict-free mod 32 for the fragment read patterns).
// mode: 0 = plain store, 1 = tf32-rounded store.
// ---------------------------------------------------------------------------
#define ASTRIDE 36
#define BSTRIDE 136
#define AFLOATS (64*ASTRIDE)            // 2304
#define STAGEF  (AFLOATS + 32*BSTRIDE)  // 6656 floats
#define SMEM_GEMM (3*STAGEF*4)          // 79872 bytes

__device__ __forceinline__ void load_stage(uint32_t sb, int s,
                                           const float* A, int lda, int bm,
                                           const float* B, int ldb, int bn,
                                           int tid, int kt) {
    uint32_t sa = sb + s * (STAGEF * 4);
    uint32_t sB = sa + AFLOATS * 4;
    int k0 = kt * 32;
    // A: 64 rows x 32 floats = 512 float4, 2 per thread
    #pragma unroll
    for (int t = 0; t < 2; t++) {
        int c = tid + t * 256;
        int row = c >> 3, col = c & 7;
        cp16(sa + row * (ASTRIDE*4) + col * 16,
             A + (size_t)(bm + row) * lda + k0 + col * 4);
    }
    // B: 32 rows x 128 floats = 1024 float4, 4 per thread
    #pragma unroll
    for (int t = 0; t < 4; t++) {
        int c = tid + t * 256;
        int row = c >> 5, col = c & 31;
        cp16(sB + row * (BSTRIDE*4) + col * 16,
             B + (size_t)(k0 + row) * ldb + bn + col * 4);
    }
}

__device__ void gemm_core(const float* __restrict__ A, int lda,
                          const float* __restrict__ B, int ldb,
                          float* __restrict__ C, int ldc,
                          int bm, int bn, int KT, int mode) {
    extern __shared__ float sm[];
    uint32_t sb = smem_u32(sm);
    int tid = threadIdx.x;
    int warp = tid >> 5, lane = tid & 31;
    int wm = (warp & 1) * 32;
    int wn = (warp >> 1) * 32;
    int tg = lane >> 2, tk = lane & 3;

    float acc[2][4][4];
    #pragma unroll
    for (int mt = 0; mt < 2; mt++)
        #pragma unroll
        for (int nt = 0; nt < 4; nt++)
            #pragma unroll
            for (int i = 0; i < 4; i++) acc[mt][nt][i] = 0.f;

    load_stage(sb, 0, A, lda, bm, B, ldb, bn, tid, 0);
    asm volatile("cp.async.commit_group;" ::: "memory");
    load_stage(sb, 1, A, lda, bm, B, ldb, bn, tid, 1);
    asm volatile("cp.async.commit_group;" ::: "memory");

    for (int it = 0; it < KT; it++) {
        asm volatile("cp.async.wait_group 1;" ::: "memory");
        __syncthreads();
        int pf = it + 2;
        if (pf < KT) load_stage(sb, pf % 3, A, lda, bm, B, ldb, bn, tid, pf);
        asm volatile("cp.async.commit_group;" ::: "memory");

        const float* As = sm + (it % 3) * STAGEF;
        const float* Bs = As + AFLOATS;
        #pragma unroll
        for (int kq = 0; kq < 32; kq += 8) {
            uint32_t af[2][4], bf[4][2];
            #pragma unroll
            for (int mt = 0; mt < 2; mt++) {
                int m = wm + mt * 16 + tg;
                af[mt][0] = __float_as_uint(As[m * ASTRIDE + kq + tk]);
                af[mt][1] = __float_as_uint(As[(m + 8) * ASTRIDE + kq + tk]);
                af[mt][2] = __float_as_uint(As[m * ASTRIDE + kq + tk + 4]);
                af[mt][3] = __float_as_uint(As[(m + 8) * ASTRIDE + kq + tk + 4]);
            }
            #pragma unroll
            for (int nt = 0; nt < 4; nt++) {
                int n = wn + nt * 8 + tg;
                bf[nt][0] = __float_as_uint(Bs[(kq + tk) * BSTRIDE + n]);
                bf[nt][1] = __float_as_uint(Bs[(kq + tk + 4) * BSTRIDE + n]);
            }
            #pragma unroll
            for (int mt = 0; mt < 2; mt++)
                #pragma unroll
                for (int nt = 0; nt < 4; nt++)
                    mma_tf32(acc[mt][nt], af[mt][0], af[mt][1], af[mt][2], af[mt][3],
                             bf[nt][0], bf[nt][1]);
        }
        __syncthreads();
    }

    #pragma unroll
    for (int mt = 0; mt < 2; mt++) {
        #pragma unroll
        for (int nt = 0; nt < 4; nt++) {
            int r0 = bm + wm + mt * 16 + tg;
            int cc = bn + wn + nt * 8 + tk * 2;
            float2 v0 = make_float2(acc[mt][nt][0], acc[mt][nt][1]);
            float2 v1 = make_float2(acc[mt][nt][2], acc[mt][nt][3]);
            if (mode == 1) {
                v0.x = rnaf(v0.x); v0.y = rnaf(v0.y);
                v1.x = rnaf(v1.x); v1.y = rnaf(v1.y);
            }
            *(float2*)&C[(size_t)r0 * ldc + cc]       = v0;
            *(float2*)&C[(size_t)(r0 + 8) * ldc + cc] = v1;
        }
    }
}

// dense wrapper: grid (N/128, M/64)
__global__ __launch_bounds__(256) void gemm_mma(const float* __restrict__ A,
                                                const float* __restrict__ Bw,
                                                float* __restrict__ C,
                                                int K, int N, int mode) {
    gemm_core(A, K, Bw, N, C, N, blockIdx.y * 64, blockIdx.x * 128, K / 32, mode);
}

// attn@V wrapper: grid (T/64, B*H), causal K clip per 64-row q tile
__global__ __launch_bounds__(256) void av_mma(const float* __restrict__ attn,
                                              const float* __restrict__ v,
                                              float* __restrict__ ctx) {
    int qt = blockIdx.x, bh = blockIdx.y;
    int b = bh >> 3, h = bh & 7;
    const float* A  = attn + (size_t)bh * Tt * Tt;
    const float* Bv = v   + (size_t)b * Tt * Dd + h * 128;
    float*       C  = ctx + (size_t)b * Tt * Dd + h * 128;
    int KT = ((qt >> 1) + 1) * 4;    // K rounded up to 128 past causal boundary
    gemm_core(A, Tt, Bv, Dd, C, Dd, qt * 64, 0, KT, 1);
}

// ---------------- staging: tf32-rna rounded copies ----------------
__global__ __launch_bounds__(256) void round_copy(const float4* __restrict__ src,
                                                  float4* __restrict__ dst, int n4) {
    int i = blockIdx.x * 256 + threadIdx.x;
    if (i < n4) {
        float4 v = src[i];
        v.x = rnaf(v.x); v.y = rnaf(v.y); v.z = rnaf(v.z); v.w = rnaf(v.w);
        dst[i] = v;
    }
}

// ---------------- paths = sigmoid(x @ Wp + bp) ----------------
__global__ __launch_bounds__(256) void paths_kernel(const float* __restrict__ x,
                                                    const float* __restrict__ Wp,
                                                    const float* __restrict__ bp) {
    __shared__ float xs[Dd];
    int tok = blockIdx.x;
    int tid = threadIdx.x;
    const float* xr = x + (size_t)tok * Dd;
    for (int i = tid; i < Dd; i += 256) xs[i] = xr[i];
    __syncthreads();
    int warp = tid >> 5, lane = tid & 31;
    #pragma unroll
    for (int j = 0; j < DEPTH; j++) {
        int col = warp * DEPTH + j;
        float s = 0.f;
        for (int k = lane; k < Dd; k += 32) s += xs[k] * Wp[k * (Hh*DEPTH) + col];
        #pragma unroll
        for (int o = 16; o > 0; o >>= 1) s += __shfl_xor_sync(0xffffffffu, s, o);
        if (lane == 0) {
            float z = s + bp[col];
            g_paths[tok * (Hh*DEPTH) + col] = 1.f / (1.f + expf(-z));
        }
    }
}

// ---------------- attn: p-adic sim + causal softmax (polynomial exp) --------
__device__ __forceinline__ float expap(float x) {   // e^x, x in (0,1], deg-7
    float p = 1.98412698e-4f;
    p = fmaf(p, x, 1.38888889e-3f);
    p = fmaf(p, x, 8.33333333e-3f);
    p = fmaf(p, x, 4.16666667e-2f);
    p = fmaf(p, x, 1.66666667e-1f);
    p = fmaf(p, x, 0.5f);
    p = fmaf(p, x, 1.0f);
    p = fmaf(p, x, 1.0f);
    return p;
}

__device__ __forceinline__ float simv(const float* pks, int k,
                                      float p0, float p1, float p2, float p3, float p4,
                                      float o0, float o1, float o2, float o3, float o4) {
    float k0 = pks[k*5+0], k1 = pks[k*5+1], k2 = pks[k*5+2], k3 = pks[k*5+3], k4 = pks[k*5+4];
    float prod = p0 * k0 + o0 * (1.f - k0);
    float s = prod;
    prod *= p1 * k1 + o1 * (1.f - k1); s += prod;
    prod *= p2 * k2 + o2 * (1.f - k2); s += prod;
    prod *= p3 * k3 + o3 * (1.f - k3); s += prod;
    prod *= p4 * k4 + o4 * (1.f - k4); s += prod;
    return s;
}

__global__ __launch_bounds__(256) void attn3_kernel(const float* __restrict__ paths,
                                                    float* __restrict__ attn) {
    __shared__ float pks[Tt * DEPTH];
    int qt = blockIdx.x, h = blockIdx.y, b = blockIdx.z;   // 64 q-rows per block
    int tid = threadIdx.x;
    int kload = (qt + 1) * 64;
    const float* pb = paths + (size_t)b * Tt * (Hh*DEPTH) + h * DEPTH;
    for (int idx = tid; idx < kload * DEPTH; idx += 256) {
        int k = idx / DEPTH, d = idx - k * DEPTH;
        pks[idx] = pb[(size_t)k * (Hh*DEPTH) + d];
    }
    __syncthreads();

    int warp = tid >> 5, lane = tid & 31;
    float* abase = attn + (size_t)((b * Hh + h) * Tt) * Tt;

    for (int r = 0; r < 8; r++) {
        int q = qt * 64 + r * 8 + warp;
        float p0 = pks[q*5+0], p1 = pks[q*5+1], p2 = pks[q*5+2],
              p3 = pks[q*5+3], p4 = pks[q*5+4];
        float o0 = 1.f - p0, o1 = 1.f - p1, o2 = 1.f - p2, o3 = 1.f - p3, o4 = 1.f - p4;
        int nit = ((q >> 7) + 1) << 2;   // iterate to 128-aligned causal boundary

        float sum = 0.f;
        #pragma unroll 4
        for (int i = 0; i < nit; i++) {
            int k = lane + i * 32;
            if (k <= q)
                sum += expap(simv(pks, k, p0,p1,p2,p3,p4, o0,o1,o2,o3,o4) * 0.2f);
        }
        #pragma unroll
        for (int o = 16; o > 0; o >>= 1) sum += __shfl_xor_sync(0xffffffffu, sum, o);
        float inv = 1.f / sum;

        float* row = abase + (size_t)q * Tt;
        #pragma unroll 4
        for (int i = 0; i < nit; i++) {
            int k = lane + i * 32;
            float ev = 0.f;
            if (k <= q)
                ev = expap(simv(pks, k, p0,p1,p2,p3,p4, o0,o1,o2,o3,o4) * 0.2f);
            row[k] = rnaf(ev * inv);
        }
    }
}

// ---------------------------------------------------------------------------
extern "C" void kernel_launch(void* const* d_in, const int* in_sizes, int n_in,
                              void* d_out, int out_size) {
    const float* x  = (const float*)d_in[0];
    const float* Wp = (const float*)d_in[1];
    const float* bp = (const float*)d_in[2];
    const float* Wv = (const float*)d_in[3];
    const float* Wo = (const float*)d_in[4];
    float* out = (float*)d_out;

    float *paths, *xr, *wvr, *wor, *v, *attn, *ctx;
    cudaGetSymbolAddress((void**)&paths, g_paths);
    cudaGetSymbolAddress((void**)&xr,    g_xr);
    cudaGetSymbolAddress((void**)&wvr,   g_wvr);
    cudaGetSymbolAddress((void**)&wor,   g_wor);
    cudaGetSymbolAddress((void**)&v,     g_v);
    cudaGetSymbolAddress((void**)&attn,  g_attn);
    cudaGetSymbolAddress((void**)&ctx,   g_ctx);

    cudaFuncSetAttribute(gemm_mma, cudaFuncAttributeMaxDynamicSharedMemorySize, SMEM_GEMM);
    cudaFuncSetAttribute(av_mma,   cudaFuncAttributeMaxDynamicSharedMemorySize, SMEM_GEMM);

    // staging: rna-rounded operands so tf32 HW truncation is lossless
    round_copy<<<(NTOK*Dd/4 + 255)/256, 256>>>((const float4*)x,  (float4*)xr,  NTOK*Dd/4);
    round_copy<<<(Dd*Dd/4 + 255)/256, 256>>>((const float4*)Wv, (float4*)wvr, Dd*Dd/4);
    round_copy<<<(Dd*Dd/4 + 255)/256, 256>>>((const float4*)Wo, (float4*)wor, Dd*Dd/4);

    paths_kernel<<<NTOK, 256>>>(x, Wp, bp);

    // V = x @ Wv (rounded store)
    gemm_mma<<<dim3(Dd/128, NTOK/64), 256, SMEM_GEMM>>>(xr, wvr, v, Dd, Dd, 1);

    attn3_kernel<<<dim3(Tt/64, Hh, Bb), 256>>>(paths, attn);

    // ctx = attn @ V (causal-clipped)
    av_mma<<<dim3(Tt/64, Bb*Hh), 256, SMEM_GEMM>>>(attn, v, ctx);

    // out = ctx @ Wo
    gemm_mma<<<dim3(Dd/128, NTOK/64), 256, SMEM_GEMM>>>(ctx, wor, out, Dd, Dd, 0);
}

// round 5
// speedup vs baseline: 2.9646x; 1.3258x over previous
#include <cuda_runtime.h>
#include <math.h>
#include <stdint.h>

#define Bb 2
#define Tt 1024
#define Dd 1024
#define Hh 8
#define DEPTH 5
#define NTOK (Bb*Tt)

// ---------------- scratch (device globals; allocation-free) ----------------
__device__ float g_paths[NTOK*Hh*DEPTH];      // [token][h*5+d]
__device__ float g_xr[NTOK*Dd];               // tf32(rna) hi part of x
__device__ float g_xlo[NTOK*Dd];              // tf32 lo residual of x
__device__ float g_wph[Dd*128];               // Wp hi, padded [k][128]
__device__ float g_wpl[Dd*128];               // Wp lo, padded [k][128]
__device__ float g_wvr[Dd*Dd];                // rounded Wv [k][n]
__device__ float g_wor[Dd*Dd];                // rounded Wo [k][n]
__device__ float g_v[NTOK*Dd];                // V = x@Wv, rounded
__device__ float g_attn[(size_t)Bb*Hh*Tt*Tt]; // attn rows (valid to causal 128-boundary)
__device__ float g_ctx[NTOK*Dd];              // ctx, rounded

// ---------------- helpers ----------------
__device__ __forceinline__ float rnaf(float f) {
    uint32_t r; asm("cvt.rna.tf32.f32 %0, %1;" : "=r"(r) : "f"(f));
    return __uint_as_float(r);
}
__device__ __forceinline__ uint32_t smem_u32(const void* p) {
    uint32_t a;
    asm("{ .reg .u64 t; cvta.to.shared.u64 t, %1; cvt.u32.u64 %0, t; }" : "=r"(a) : "l"(p));
    return a;
}
__device__ __forceinline__ void cp16(uint32_t dst, const void* src) {
    asm volatile("cp.async.cg.shared.global [%0], [%1], 16;" :: "r"(dst), "l"(src));
}
__device__ __forceinline__ void mma_tf32(float c[4],
                                         uint32_t a0, uint32_t a1, uint32_t a2, uint32_t a3,
                                         uint32_t b0, uint32_t b1) {
    asm volatile("mma.sync.aligned.m16n8k8.row.col.f32.tf32.tf32.f32 "
                 "{%0,%1,%2,%3}, {%4,%5,%6,%7}, {%8,%9}, {%0,%1,%2,%3};"
                 : "+f"(c[0]), "+f"(c[1]), "+f"(c[2]), "+f"(c[3])
                 : "r"(a0), "r"(a1), "r"(a2), "r"(a3), "r"(b0), "r"(b1));
}

// ---------------------------------------------------------------------------
// Main tf32 GEMM core (as round 4): C[64,128] tile, 8 warps, BK=32, 3-stage.
// ---------------------------------------------------------------------------
#define ASTRIDE 36
#define BSTRIDE 136
#define AFLOATS (64*ASTRIDE)
#define STAGEF  (AFLOATS + 32*BSTRIDE)
#define SMEM_GEMM (3*STAGEF*4)

__device__ __forceinline__ void load_stage(uint32_t sb, int s,
                                           const float* A, int lda, int bm,
                                           const float* B, int ldb, int bn,
                                           int tid, int kt) {
    uint32_t sa = sb + s * (STAGEF * 4);
    uint32_t sB = sa + AFLOATS * 4;
    int k0 = kt * 32;
    #pragma unroll
    for (int t = 0; t < 2; t++) {
        int c = tid + t * 256;
        int row = c >> 3, col = c & 7;
        cp16(sa + row * (ASTRIDE*4) + col * 16,
             A + (size_t)(bm + row) * lda + k0 + col * 4);
    }
    #pragma unroll
    for (int t = 0; t < 4; t++) {
        int c = tid + t * 256;
        int row = c >> 5, col = c & 31;
        cp16(sB + row * (BSTRIDE*4) + col * 16,
             B + (size_t)(k0 + row) * ldb + bn + col * 4);
    }
}

__device__ void gemm_core(const float* __restrict__ A, int lda,
                          const float* __restrict__ B, int ldb,
                          float* __restrict__ C, int ldc,
                          int bm, int bn, int KT, int mode) {
    extern __shared__ float sm[];
    uint32_t sb = smem_u32(sm);
    int tid = threadIdx.x;
    int warp = tid >> 5, lane = tid & 31;
    int wm = (warp & 1) * 32;
    int wn = (warp >> 1) * 32;
    int tg = lane >> 2, tk = lane & 3;

    float acc[2][4][4];
    #pragma unroll
    for (int mt = 0; mt < 2; mt++)
        #pragma unroll
        for (int nt = 0; nt < 4; nt++)
            #pragma unroll
            for (int i = 0; i < 4; i++) acc[mt][nt][i] = 0.f;

    load_stage(sb, 0, A, lda, bm, B, ldb, bn, tid, 0);
    asm volatile("cp.async.commit_group;" ::: "memory");
    load_stage(sb, 1, A, lda, bm, B, ldb, bn, tid, 1);
    asm volatile("cp.async.commit_group;" ::: "memory");

    for (int it = 0; it < KT; it++) {
        asm volatile("cp.async.wait_group 1;" ::: "memory");
        __syncthreads();
        int pf = it + 2;
        if (pf < KT) load_stage(sb, pf % 3, A, lda, bm, B, ldb, bn, tid, pf);
        asm volatile("cp.async.commit_group;" ::: "memory");

        const float* As = sm + (it % 3) * STAGEF;
        const float* Bs = As + AFLOATS;
        #pragma unroll
        for (int kq = 0; kq < 32; kq += 8) {
            uint32_t af[2][4], bf[4][2];
            #pragma unroll
            for (int mt = 0; mt < 2; mt++) {
                int m = wm + mt * 16 + tg;
                af[mt][0] = __float_as_uint(As[m * ASTRIDE + kq + tk]);
                af[mt][1] = __float_as_uint(As[(m + 8) * ASTRIDE + kq + tk]);
                af[mt][2] = __float_as_uint(As[m * ASTRIDE + kq + tk + 4]);
                af[mt][3] = __float_as_uint(As[(m + 8) * ASTRIDE + kq + tk + 4]);
            }
            #pragma unroll
            for (int nt = 0; nt < 4; nt++) {
                int n = wn + nt * 8 + tg;
                bf[nt][0] = __float_as_uint(Bs[(kq + tk) * BSTRIDE + n]);
                bf[nt][1] = __float_as_uint(Bs[(kq + tk + 4) * BSTRIDE + n]);
            }
            #pragma unroll
            for (int mt = 0; mt < 2; mt++)
                #pragma unroll
                for (int nt = 0; nt < 4; nt++)
                    mma_tf32(acc[mt][nt], af[mt][0], af[mt][1], af[mt][2], af[mt][3],
                             bf[nt][0], bf[nt][1]);
        }
        __syncthreads();
    }

    #pragma unroll
    for (int mt = 0; mt < 2; mt++) {
        #pragma unroll
        for (int nt = 0; nt < 4; nt++) {
            int r0 = bm + wm + mt * 16 + tg;
            int cc = bn + wn + nt * 8 + tk * 2;
            float2 v0 = make_float2(acc[mt][nt][0], acc[mt][nt][1]);
            float2 v1 = make_float2(acc[mt][nt][2], acc[mt][nt][3]);
            if (mode == 1) {
                v0.x = rnaf(v0.x); v0.y = rnaf(v0.y);
                v1.x = rnaf(v1.x); v1.y = rnaf(v1.y);
            }
            *(float2*)&C[(size_t)r0 * ldc + cc]       = v0;
            *(float2*)&C[(size_t)(r0 + 8) * ldc + cc] = v1;
        }
    }
}

__global__ __launch_bounds__(256) void gemm_mma(const float* __restrict__ A,
                                                const float* __restrict__ Bw,
                                                float* __restrict__ C,
                                                int K, int N, int mode) {
    gemm_core(A, K, Bw, N, C, N, blockIdx.y * 64, blockIdx.x * 128, K / 32, mode);
}

__global__ __launch_bounds__(256) void av_mma(const float* __restrict__ attn,
                                              const float* __restrict__ v,
                                              float* __restrict__ ctx) {
    int qt = blockIdx.x, bh = blockIdx.y;
    int b = bh >> 3, h = bh & 7;
    const float* A  = attn + (size_t)bh * Tt * Tt;
    const float* Bv = v   + (size_t)b * Tt * Dd + h * 128;
    float*       C  = ctx + (size_t)b * Tt * Dd + h * 128;
    int KT = ((qt >> 1) + 1) * 4;
    gemm_core(A, Tt, Bv, Dd, C, Dd, qt * 64, 0, KT, 1);
}

// ---------------------------------------------------------------------------
// paths GEMM: logits = x @ Wp_pad via split-tf32 (hi*hi + hi*lo + lo*hi),
// fused sigmoid(+bp) epilogue -> compact g_paths[tok][40].
// BM=64, BN=128(pad, 40 valid), K=1024, 2-stage cp.async. Grid = 32 CTAs.
// ---------------------------------------------------------------------------
#define PSTAGEF (2*64*36 + 2*32*136)    // xh,xl + wh,wl = 13312 floats
#define SMEM_PATHS (2*PSTAGEF*4)        // 106496 bytes

__device__ __forceinline__ void paths_load(uint32_t sb, int s,
                                           const float* xh, const float* xl, int bm,
                                           const float* wh, const float* wl,
                                           int tid, int kt) {
    uint32_t base = sb + s * (PSTAGEF * 4);
    uint32_t xh_o = base;
    uint32_t xl_o = base + 64*36*4;
    uint32_t wh_o = xl_o + 64*36*4;
    uint32_t wl_o = wh_o + 32*136*4;
    int k0 = kt * 32;
    #pragma unroll
    for (int t = 0; t < 2; t++) {
        int c = tid + t * 256;
        int row = c >> 3, col = c & 7;
        size_t go = (size_t)(bm + row) * Dd + k0 + col * 4;
        uint32_t so = row * (36*4) + col * 16;
        cp16(xh_o + so, xh + go);
        cp16(xl_o + so, xl + go);
    }
    #pragma unroll
    for (int t = 0; t < 4; t++) {
        int c = tid + t * 256;
        int row = c >> 5, col = c & 31;
        size_t go = (size_t)(k0 + row) * 128 + col * 4;
        uint32_t so = row * (136*4) + col * 16;
        cp16(wh_o + so, wh + go);
        cp16(wl_o + so, wl + go);
    }
}

__global__ __launch_bounds__(256) void paths_gemm(const float* __restrict__ xh,
                                                  const float* __restrict__ xl,
                                                  const float* __restrict__ wh,
                                                  const float* __restrict__ wl,
                                                  const float* __restrict__ bp,
                                                  float* __restrict__ paths) {
    extern __shared__ float sm[];
    uint32_t sb = smem_u32(sm);
    int tid = threadIdx.x;
    int warp = tid >> 5, lane = tid & 31;
    int wm = (warp & 1) * 32;
    int wn = (warp >> 1) * 32;
    int tg = lane >> 2, tk = lane & 3;
    int bm = blockIdx.x * 64;

    float acc[2][4][4];
    #pragma unroll
    for (int mt = 0; mt < 2; mt++)
        #pragma unroll
        for (int nt = 0; nt < 4; nt++)
            #pragma unroll
            for (int i = 0; i < 4; i++) acc[mt][nt][i] = 0.f;

    paths_load(sb, 0, xh, xl, bm, wh, wl, tid, 0);
    asm volatile("cp.async.commit_group;" ::: "memory");

    for (int it = 0; it < 32; it++) {
        int pf = it + 1;
        if (pf < 32) {
            paths_load(sb, pf & 1, xh, xl, bm, wh, wl, tid, pf);
            asm volatile("cp.async.commit_group;" ::: "memory");
            asm volatile("cp.async.wait_group 1;" ::: "memory");
        } else {
            asm volatile("cp.async.wait_group 0;" ::: "memory");
        }
        __syncthreads();

        const float* Xh = sm + (it & 1) * PSTAGEF;
        const float* Xl = Xh + 64*36;
        const float* Wh = Xl + 64*36;
        const float* Wl = Wh + 32*136;
        #pragma unroll
        for (int kq = 0; kq < 32; kq += 8) {
            uint32_t ah[2][4], al[2][4], bh[4][2], bl[4][2];
            #pragma unroll
            for (int mt = 0; mt < 2; mt++) {
                int m = wm + mt * 16 + tg;
                ah[mt][0] = __float_as_uint(Xh[m * 36 + kq + tk]);
                ah[mt][1] = __float_as_uint(Xh[(m + 8) * 36 + kq + tk]);
                ah[mt][2] = __float_as_uint(Xh[m * 36 + kq + tk + 4]);
                ah[mt][3] = __float_as_uint(Xh[(m + 8) * 36 + kq + tk + 4]);
                al[mt][0] = __float_as_uint(Xl[m * 36 + kq + tk]);
                al[mt][1] = __float_as_uint(Xl[(m + 8) * 36 + kq + tk]);
                al[mt][2] = __float_as_uint(Xl[m * 36 + kq + tk + 4]);
                al[mt][3] = __float_as_uint(Xl[(m + 8) * 36 + kq + tk + 4]);
            }
            #pragma unroll
            for (int nt = 0; nt < 4; nt++) {
                int n = wn + nt * 8 + tg;
                bh[nt][0] = __float_as_uint(Wh[(kq + tk) * 136 + n]);
                bh[nt][1] = __float_as_uint(Wh[(kq + tk + 4) * 136 + n]);
                bl[nt][0] = __float_as_uint(Wl[(kq + tk) * 136 + n]);
                bl[nt][1] = __float_as_uint(Wl[(kq + tk + 4) * 136 + n]);
            }
            #pragma unroll
            for (int mt = 0; mt < 2; mt++)
                #pragma unroll
                for (int nt = 0; nt < 4; nt++) {
                    mma_tf32(acc[mt][nt], ah[mt][0], ah[mt][1], ah[mt][2], ah[mt][3],
                             bh[nt][0], bh[nt][1]);
                    mma_tf32(acc[mt][nt], ah[mt][0], ah[mt][1], ah[mt][2], ah[mt][3],
                             bl[nt][0], bl[nt][1]);
                    mma_tf32(acc[mt][nt], al[mt][0], al[mt][1], al[mt][2], al[mt][3],
                             bh[nt][0], bh[nt][1]);
                }
        }
        __syncthreads();
    }

    #pragma unroll
    for (int mt = 0; mt < 2; mt++) {
        #pragma unroll
        for (int nt = 0; nt < 4; nt++) {
            int cc = wn + nt * 8 + tk * 2;
            if (cc < Hh * DEPTH) {
                int r0 = bm + wm + mt * 16 + tg;
                float b0 = bp[cc], b1 = bp[cc + 1];
                paths[(size_t)r0 * 40 + cc]           = 1.f / (1.f + expf(-(acc[mt][nt][0] + b0)));
                paths[(size_t)r0 * 40 + cc + 1]       = 1.f / (1.f + expf(-(acc[mt][nt][1] + b1)));
                paths[(size_t)(r0 + 8) * 40 + cc]     = 1.f / (1.f + expf(-(acc[mt][nt][2] + b0)));
                paths[(size_t)(r0 + 8) * 40 + cc + 1] = 1.f / (1.f + expf(-(acc[mt][nt][3] + b1)));
            }
        }
    }
}

// ---------------- staging kernels ----------------
__global__ __launch_bounds__(256) void split_copy(const float4* __restrict__ src,
                                                  float4* __restrict__ hi,
                                                  float4* __restrict__ lo, int n4) {
    int i = blockIdx.x * 256 + threadIdx.x;
    if (i < n4) {
        float4 v = src[i];
        float4 h = make_float4(rnaf(v.x), rnaf(v.y), rnaf(v.z), rnaf(v.w));
        hi[i] = h;
        lo[i] = make_float4(rnaf(v.x - h.x), rnaf(v.y - h.y), rnaf(v.z - h.z), rnaf(v.w - h.w));
    }
}
__global__ __launch_bounds__(256) void round_copy(const float4* __restrict__ src,
                                                  float4* __restrict__ dst, int n4) {
    int i = blockIdx.x * 256 + threadIdx.x;
    if (i < n4) {
        float4 v = src[i];
        dst[i] = make_float4(rnaf(v.x), rnaf(v.y), rnaf(v.z), rnaf(v.w));
    }
}
__global__ void wp_prep(const float* __restrict__ Wp) {   // [1024][40] -> hi/lo padded [1024][128]
    int k = blockIdx.x, n = threadIdx.x;
    float h = 0.f, l = 0.f;
    if (n < Hh * DEPTH) {
        float w = Wp[(size_t)k * (Hh * DEPTH) + n];
        h = rnaf(w);
        l = rnaf(w - h);
    }
    g_wph[(size_t)k * 128 + n] = h;
    g_wpl[(size_t)k * 128 + n] = l;
}

// ---------------- attn: p-adic sim + causal softmax ----------------
__device__ __forceinline__ float expap(float x) {   // e^x, x in (0,1], deg-7
    float p = 1.98412698e-4f;
    p = fmaf(p, x, 1.38888889e-3f);
    p = fmaf(p, x, 8.33333333e-3f);
    p = fmaf(p, x, 4.16666667e-2f);
    p = fmaf(p, x, 1.66666667e-1f);
    p = fmaf(p, x, 0.5f);
    p = fmaf(p, x, 1.0f);
    p = fmaf(p, x, 1.0f);
    return p;
}

__device__ __forceinline__ float simv(const float* pks, int k,
                                      float p0, float p1, float p2, float p3, float p4,
                                      float o0, float o1, float o2, float o3, float o4) {
    float k0 = pks[k*5+0], k1 = pks[k*5+1], k2 = pks[k*5+2], k3 = pks[k*5+3], k4 = pks[k*5+4];
    float prod = p0 * k0 + o0 * (1.f - k0);
    float s = prod;
    prod *= p1 * k1 + o1 * (1.f - k1); s += prod;
    prod *= p2 * k2 + o2 * (1.f - k2); s += prod;
    prod *= p3 * k3 + o3 * (1.f - k3); s += prod;
    prod *= p4 * k4 + o4 * (1.f - k4); s += prod;
    return s;
}

__global__ __launch_bounds__(256) void attn3_kernel(const float* __restrict__ paths,
                                                    float* __restrict__ attn) {
    __shared__ float pks[Tt * DEPTH];
    int qt = blockIdx.x, h = blockIdx.y, b = blockIdx.z;
    int tid = threadIdx.x;
    int kload = (qt + 1) * 64;
    const float* pb = paths + (size_t)b * Tt * (Hh*DEPTH) + h * DEPTH;
    for (int idx = tid; idx < kload * DEPTH; idx += 256) {
        int k = idx / DEPTH, d = idx - k * DEPTH;
        pks[idx] = pb[(size_t)k * (Hh*DEPTH) + d];
    }
    __syncthreads();

    int warp = tid >> 5, lane = tid & 31;
    float* abase = attn + (size_t)((b * Hh + h) * Tt) * Tt;

    for (int r = 0; r < 8; r++) {
        int q = qt * 64 + r * 8 + warp;
        float p0 = pks[q*5+0], p1 = pks[q*5+1], p2 = pks[q*5+2],
              p3 = pks[q*5+3], p4 = pks[q*5+4];
        float o0 = 1.f - p0, o1 = 1.f - p1, o2 = 1.f - p2, o3 = 1.f - p3, o4 = 1.f - p4;
        int nit = ((q >> 7) + 1) << 2;

        float sum = 0.f;
        #pragma unroll 4
        for (int i = 0; i < nit; i++) {
            int k = lane + i * 32;
            if (k <= q)
                sum += expap(simv(pks, k, p0,p1,p2,p3,p4, o0,o1,o2,o3,o4) * 0.2f);
        }
        #pragma unroll
        for (int o = 16; o > 0; o >>= 1) sum += __shfl_xor_sync(0xffffffffu, sum, o);
        float inv = 1.f / sum;

        float* row = abase + (size_t)q * Tt;
        #pragma unroll 4
        for (int i = 0; i < nit; i++) {
            int k = lane + i * 32;
            float ev = 0.f;
            if (k <= q)
                ev = expap(simv(pks, k, p0,p1,p2,p3,p4, o0,o1,o2,o3,o4) * 0.2f);
            row[k] = rnaf(ev * inv);
        }
    }
}

// ---------------------------------------------------------------------------
extern "C" void kernel_launch(void* const* d_in, const int* in_sizes, int n_in,
                              void* d_out, int out_size) {
    const float* x  = (const float*)d_in[0];
    const float* Wp = (const float*)d_in[1];
    const float* bp = (const float*)d_in[2];
    const float* Wv = (const float*)d_in[3];
    const float* Wo = (const float*)d_in[4];
    float* out = (float*)d_out;

    float *paths, *xr, *xlo, *wph, *wpl, *wvr, *wor, *v, *attn, *ctx;
    cudaGetSymbolAddress((void**)&paths, g_paths);
    cudaGetSymbolAddress((void**)&xr,    g_xr);
    cudaGetSymbolAddress((void**)&xlo,   g_xlo);
    cudaGetSymbolAddress((void**)&wph,   g_wph);
    cudaGetSymbolAddress((void**)&wpl,   g_wpl);
    cudaGetSymbolAddress((void**)&wvr,   g_wvr);
    cudaGetSymbolAddress((void**)&wor,   g_wor);
    cudaGetSymbolAddress((void**)&v,     g_v);
    cudaGetSymbolAddress((void**)&attn,  g_attn);
    cudaGetSymbolAddress((void**)&ctx,   g_ctx);

    cudaFuncSetAttribute(gemm_mma,   cudaFuncAttributeMaxDynamicSharedMemorySize, SMEM_GEMM);
    cudaFuncSetAttribute(av_mma,     cudaFuncAttributeMaxDynamicSharedMemorySize, SMEM_GEMM);
    cudaFuncSetAttribute(paths_gemm, cudaFuncAttributeMaxDynamicSharedMemorySize, SMEM_PATHS);

    // staging
    split_copy<<<(NTOK*Dd/4 + 255)/256, 256>>>((const float4*)x, (float4*)xr, (float4*)xlo, NTOK*Dd/4);
    round_copy<<<(Dd*Dd/4 + 255)/256, 256>>>((const float4*)Wv, (float4*)wvr, Dd*Dd/4);
    round_copy<<<(Dd*Dd/4 + 255)/256, 256>>>((const float4*)Wo, (float4*)wor, Dd*Dd/4);
    wp_prep<<<Dd, 128>>>(Wp);

    // paths = sigmoid(x @ Wp + bp) — split-tf32 GEMM, fused sigmoid
    paths_gemm<<<NTOK/64, 256, SMEM_PATHS>>>(xr, xlo, wph, wpl, bp, paths);

    // V = x @ Wv (rounded store)
    gemm_mma<<<dim3(Dd/128, NTOK/64), 256, SMEM_GEMM>>>(xr, wvr, v, Dd, Dd, 1);

    attn3_kernel<<<dim3(Tt/64, Hh, Bb), 256>>>(paths, attn);

    // ctx = attn @ V (causal-clipped)
    av_mma<<<dim3(Tt/64, Bb*Hh), 256, SMEM_GEMM>>>(attn, v, ctx);

    // out = ctx @ Wo
    gemm_mma<<<dim3(Dd/128, NTOK/64), 256, SMEM_GEMM>>>(ctx, wor, out, Dd, Dd, 0);
}

// round 6
// speedup vs baseline: 3.9402x; 1.3291x over previous
#include <cuda_runtime.h>
#include <math.h>
#include <stdint.h>

#define Bb 2
#define Tt 1024
#define Dd 1024
#define Hh 8
#define DEPTH 5
#define NTOK (Bb*Tt)

// ---------------- scratch (device globals; allocation-free) ----------------
__device__ float g_paths[NTOK*Hh*DEPTH];      // [token][h*5+d]
__device__ float g_xr[NTOK*Dd];               // tf32(rna) hi part of x
__device__ float g_xlo[NTOK*Dd];              // tf32 lo residual of x
__device__ float g_wph[Dd*128];               // Wp hi, padded [k][128]
__device__ float g_wpl[Dd*128];               // Wp lo, padded [k][128]
__device__ float g_pp[4*NTOK*128];            // paths split-K partial logits
__device__ float g_wvr[Dd*Dd];                // rounded Wv [k][n]
__device__ float g_wor[Dd*Dd];                // rounded Wo [k][n]
__device__ float g_v[NTOK*Dd];                // V = x@Wv, rounded
__device__ float g_attn[(size_t)Bb*Hh*Tt*Tt]; // attn rows (valid to causal 128-boundary)
__device__ float g_ctx[NTOK*Dd];              // ctx partial (half0 / full tiles)
__device__ float g_ctx2[NTOK*Dd];             // ctx partial (half1; zeroed)

// av job tables: 26 jobs per bh. qt<6 full; qt>=6 split into two K-halves.
__constant__ int c_qt[26] = {0,1,2,3,4,5, 6,6,7,7, 8,8,9,9, 10,10,11,11, 12,12,13,13, 14,14,15,15};
__constant__ int c_k0[26] = {0,0,0,0,0,0, 0,8,0,8, 0,10,0,10, 0,12,0,12, 0,14,0,14, 0,16,0,16};
__constant__ int c_kt[26] = {4,4,8,8,12,12, 8,8,8,8, 10,10,10,10, 12,12,12,12, 14,14,14,14, 16,16,16,16};
__constant__ int c_ds[26] = {0,0,0,0,0,0, 0,1,0,1, 0,1,0,1, 0,1,0,1, 0,1,0,1, 0,1,0,1};

// ---------------- helpers ----------------
__device__ __forceinline__ float rnaf(float f) {
    uint32_t r; asm("cvt.rna.tf32.f32 %0, %1;" : "=r"(r) : "f"(f));
    return __uint_as_float(r);
}
__device__ __forceinline__ uint32_t smem_u32(const void* p) {
    uint32_t a;
    asm("{ .reg .u64 t; cvta.to.shared.u64 t, %1; cvt.u32.u64 %0, t; }" : "=r"(a) : "l"(p));
    return a;
}
__device__ __forceinline__ void cp16(uint32_t dst, const void* src) {
    asm volatile("cp.async.cg.shared.global [%0], [%1], 16;" :: "r"(dst), "l"(src));
}
__device__ __forceinline__ void mma_tf32(float c[4],
                                         uint32_t a0, uint32_t a1, uint32_t a2, uint32_t a3,
                                         uint32_t b0, uint32_t b1) {
    asm volatile("mma.sync.aligned.m16n8k8.row.col.f32.tf32.tf32.f32 "
                 "{%0,%1,%2,%3}, {%4,%5,%6,%7}, {%8,%9}, {%0,%1,%2,%3};"
                 : "+f"(c[0]), "+f"(c[1]), "+f"(c[2]), "+f"(c[3])
                 : "r"(a0), "r"(a1), "r"(a2), "r"(a3), "r"(b0), "r"(b1));
}

// ---------------------------------------------------------------------------
// tf32 GEMM core: C[64,128] tile, 8 warps, BK=32, 3-stage cp.async.
// ---------------------------------------------------------------------------
#define ASTRIDE 36
#define BSTRIDE 136
#define AFLOATS (64*ASTRIDE)
#define STAGEF  (AFLOATS + 32*BSTRIDE)
#define SMEM_GEMM (3*STAGEF*4)

__device__ __forceinline__ void load_stage(uint32_t sb, int s,
                                           const float* A, int lda, int bm,
                                           const float* B, int ldb, int bn,
                                           int tid, int kt) {
    uint32_t sa = sb + s * (STAGEF * 4);
    uint32_t sB = sa + AFLOATS * 4;
    int k0 = kt * 32;
    #pragma unroll
    for (int t = 0; t < 2; t++) {
        int c = tid + t * 256;
        int row = c >> 3, col = c & 7;
        cp16(sa + row * (ASTRIDE*4) + col * 16,
             A + (size_t)(bm + row) * lda + k0 + col * 4);
    }
    #pragma unroll
    for (int t = 0; t < 4; t++) {
        int c = tid + t * 256;
        int row = c >> 5, col = c & 31;
        cp16(sB + row * (BSTRIDE*4) + col * 16,
             B + (size_t)(k0 + row) * ldb + bn + col * 4);
    }
}

__device__ void gemm_core(const float* __restrict__ A, int lda,
                          const float* __restrict__ B, int ldb,
                          float* __restrict__ C, int ldc,
                          int bm, int bn, int KT, int mode) {
    extern __shared__ float sm[];
    uint32_t sb = smem_u32(sm);
    int tid = threadIdx.x;
    int warp = tid >> 5, lane = tid & 31;
    int wm = (warp & 1) * 32;
    int wn = (warp >> 1) * 32;
    int tg = lane >> 2, tk = lane & 3;

    float acc[2][4][4];
    #pragma unroll
    for (int mt = 0; mt < 2; mt++)
        #pragma unroll
        for (int nt = 0; nt < 4; nt++)
            #pragma unroll
            for (int i = 0; i < 4; i++) acc[mt][nt][i] = 0.f;

    load_stage(sb, 0, A, lda, bm, B, ldb, bn, tid, 0);
    asm volatile("cp.async.commit_group;" ::: "memory");
    load_stage(sb, 1, A, lda, bm, B, ldb, bn, tid, 1);
    asm volatile("cp.async.commit_group;" ::: "memory");

    for (int it = 0; it < KT; it++) {
        asm volatile("cp.async.wait_group 1;" ::: "memory");
        __syncthreads();
        int pf = it + 2;
        if (pf < KT) load_stage(sb, pf % 3, A, lda, bm, B, ldb, bn, tid, pf);
        asm volatile("cp.async.commit_group;" ::: "memory");

        const float* As = sm + (it % 3) * STAGEF;
        const float* Bs = As + AFLOATS;
        #pragma unroll
        for (int kq = 0; kq < 32; kq += 8) {
            uint32_t af[2][4], bf[4][2];
            #pragma unroll
            for (int mt = 0; mt < 2; mt++) {
                int m = wm + mt * 16 + tg;
                af[mt][0] = __float_as_uint(As[m * ASTRIDE + kq + tk]);
                af[mt][1] = __float_as_uint(As[(m + 8) * ASTRIDE + kq + tk]);
                af[mt][2] = __float_as_uint(As[m * ASTRIDE + kq + tk + 4]);
                af[mt][3] = __float_as_uint(As[(m + 8) * ASTRIDE + kq + tk + 4]);
            }
            #pragma unroll
            for (int nt = 0; nt < 4; nt++) {
                int n = wn + nt * 8 + tg;
                bf[nt][0] = __float_as_uint(Bs[(kq + tk) * BSTRIDE + n]);
                bf[nt][1] = __float_as_uint(Bs[(kq + tk + 4) * BSTRIDE + n]);
            }
            #pragma unroll
            for (int mt = 0; mt < 2; mt++)
                #pragma unroll
                for (int nt = 0; nt < 4; nt++)
                    mma_tf32(acc[mt][nt], af[mt][0], af[mt][1], af[mt][2], af[mt][3],
                             bf[nt][0], bf[nt][1]);
        }
        __syncthreads();
    }

    #pragma unroll
    for (int mt = 0; mt < 2; mt++) {
        #pragma unroll
        for (int nt = 0; nt < 4; nt++) {
            int r0 = bm + wm + mt * 16 + tg;
            int cc = bn + wn + nt * 8 + tk * 2;
            float2 v0 = make_float2(acc[mt][nt][0], acc[mt][nt][1]);
            float2 v1 = make_float2(acc[mt][nt][2], acc[mt][nt][3]);
            if (mode == 1) {
                v0.x = rnaf(v0.x); v0.y = rnaf(v0.y);
                v1.x = rnaf(v1.x); v1.y = rnaf(v1.y);
            }
            *(float2*)&C[(size_t)r0 * ldc + cc]       = v0;
            *(float2*)&C[(size_t)(r0 + 8) * ldc + cc] = v1;
        }
    }
}

__global__ __launch_bounds__(256) void gemm_mma(const float* __restrict__ A,
                                                const float* __restrict__ Bw,
                                                float* __restrict__ C,
                                                int K, int N, int mode) {
    gemm_core(A, K, Bw, N, C, N, blockIdx.y * 64, blockIdx.x * 128, K / 32, mode);
}

// balanced attn@V: grid (26, B*H); jobs from constant tables, split tiles
// write their second K-half into ctx2 (combined later).
__global__ __launch_bounds__(256) void av_mma(const float* __restrict__ attn,
                                              const float* __restrict__ v,
                                              float* __restrict__ ctx,
                                              float* __restrict__ ctx2) {
    int j = blockIdx.x, bh = blockIdx.y;
    int qt = c_qt[j], k0t = c_k0[j], KT = c_kt[j];
    int b = bh >> 3, h = bh & 7;
    const float* A  = attn + (size_t)bh * Tt * Tt + k0t * 32;
    const float* Bv = v + (size_t)b * Tt * Dd + h * 128 + (size_t)(k0t * 32) * Dd;
    float* C = (c_ds[j] ? ctx2 : ctx) + (size_t)b * Tt * Dd + h * 128;
    gemm_core(A, Tt, Bv, Dd, C, Dd, qt * 64, 0, KT, 0);
}

// ---------------------------------------------------------------------------
// paths GEMM, split-K x4: partial logits = x @ Wp_pad (split-tf32, 3 mma).
// grid (NTOK/64, 4). Each CTA does K=256 (8 iters of 32).
// ---------------------------------------------------------------------------
#define PSTAGEF (2*64*36 + 2*32*136)
#define SMEM_PATHS (2*PSTAGEF*4)

__device__ __forceinline__ void paths_load(uint32_t sb, int s,
                                           const float* xh, const float* xl, int bm,
                                           const float* wh, const float* wl,
                                           int tid, int kt) {
    uint32_t base = sb + s * (PSTAGEF * 4);
    uint32_t xh_o = base;
    uint32_t xl_o = base + 64*36*4;
    uint32_t wh_o = xl_o + 64*36*4;
    uint32_t wl_o = wh_o + 32*136*4;
    int k0 = kt * 32;
    #pragma unroll
    for (int t = 0; t < 2; t++) {
        int c = tid + t * 256;
        int row = c >> 3, col = c & 7;
        size_t go = (size_t)(bm + row) * Dd + k0 + col * 4;
        uint32_t so = row * (36*4) + col * 16;
        cp16(xh_o + so, xh + go);
        cp16(xl_o + so, xl + go);
    }
    #pragma unroll
    for (int t = 0; t < 4; t++) {
        int c = tid + t * 256;
        int row = c >> 5, col = c & 31;
        size_t go = (size_t)(k0 + row) * 128 + col * 4;
        uint32_t so = row * (136*4) + col * 16;
        cp16(wh_o + so, wh + go);
        cp16(wl_o + so, wl + go);
    }
}

__global__ __launch_bounds__(256) void paths_gemm(const float* __restrict__ xh0,
                                                  const float* __restrict__ xl0,
                                                  const float* __restrict__ wh0,
                                                  const float* __restrict__ wl0,
                                                  float* __restrict__ pp) {
    extern __shared__ float sm[];
    uint32_t sb = smem_u32(sm);
    int tid = threadIdx.x;
    int warp = tid >> 5, lane = tid & 31;
    int wm = (warp & 1) * 32;
    int wn = (warp >> 1) * 32;
    int tg = lane >> 2, tk = lane & 3;
    int bm = blockIdx.x * 64;
    int sp = blockIdx.y;
    const float* xh = xh0 + sp * 256;                  // K offset (columns)
    const float* xl = xl0 + sp * 256;
    const float* wh = wh0 + (size_t)(sp * 256) * 128;  // K offset (rows)
    const float* wl = wl0 + (size_t)(sp * 256) * 128;
    float* out = pp + (size_t)sp * NTOK * 128;
    const int KT = 8;

    float acc[2][4][4];
    #pragma unroll
    for (int mt = 0; mt < 2; mt++)
        #pragma unroll
        for (int nt = 0; nt < 4; nt++)
            #pragma unroll
            for (int i = 0; i < 4; i++) acc[mt][nt][i] = 0.f;

    paths_load(sb, 0, xh, xl, bm, wh, wl, tid, 0);
    asm volatile("cp.async.commit_group;" ::: "memory");

    for (int it = 0; it < KT; it++) {
        int pf = it + 1;
        if (pf < KT) {
            paths_load(sb, pf & 1, xh, xl, bm, wh, wl, tid, pf);
            asm volatile("cp.async.commit_group;" ::: "memory");
            asm volatile("cp.async.wait_group 1;" ::: "memory");
        } else {
            asm volatile("cp.async.wait_group 0;" ::: "memory");
        }
        __syncthreads();

        const float* Xh = sm + (it & 1) * PSTAGEF;
        const float* Xl = Xh + 64*36;
        const float* Wh = Xl + 64*36;
        const float* Wl = Wh + 32*136;
        #pragma unroll
        for (int kq = 0; kq < 32; kq += 8) {
            uint32_t ah[2][4], al[2][4], bh[4][2], bl[4][2];
            #pragma unroll
            for (int mt = 0; mt < 2; mt++) {
                int m = wm + mt * 16 + tg;
                ah[mt][0] = __float_as_uint(Xh[m * 36 + kq + tk]);
                ah[mt][1] = __float_as_uint(Xh[(m + 8) * 36 + kq + tk]);
                ah[mt][2] = __float_as_uint(Xh[m * 36 + kq + tk + 4]);
                ah[mt][3] = __float_as_uint(Xh[(m + 8) * 36 + kq + tk + 4]);
                al[mt][0] = __float_as_uint(Xl[m * 36 + kq + tk]);
                al[mt][1] = __float_as_uint(Xl[(m + 8) * 36 + kq + tk]);
                al[mt][2] = __float_as_uint(Xl[m * 36 + kq + tk + 4]);
                al[mt][3] = __float_as_uint(Xl[(m + 8) * 36 + kq + tk + 4]);
            }
            #pragma unroll
            for (int nt = 0; nt < 4; nt++) {
                int n = wn + nt * 8 + tg;
                bh[nt][0] = __float_as_uint(Wh[(kq + tk) * 136 + n]);
                bh[nt][1] = __float_as_uint(Wh[(kq + tk + 4) * 136 + n]);
                bl[nt][0] = __float_as_uint(Wl[(kq + tk) * 136 + n]);
                bl[nt][1] = __float_as_uint(Wl[(kq + tk + 4) * 136 + n]);
            }
            #pragma unroll
            for (int mt = 0; mt < 2; mt++)
                #pragma unroll
                for (int nt = 0; nt < 4; nt++) {
                    mma_tf32(acc[mt][nt], ah[mt][0], ah[mt][1], ah[mt][2], ah[mt][3],
                             bh[nt][0], bh[nt][1]);
                    mma_tf32(acc[mt][nt], ah[mt][0], ah[mt][1], ah[mt][2], ah[mt][3],
                             bl[nt][0], bl[nt][1]);
                    mma_tf32(acc[mt][nt], al[mt][0], al[mt][1], al[mt][2], al[mt][3],
                             bh[nt][0], bh[nt][1]);
                }
        }
        __syncthreads();
    }

    #pragma unroll
    for (int mt = 0; mt < 2; mt++) {
        #pragma unroll
        for (int nt = 0; nt < 4; nt++) {
            int cc = wn + nt * 8 + tk * 2;
            if (cc < Hh * DEPTH) {
                int r0 = bm + wm + mt * 16 + tg;
                out[(size_t)r0 * 128 + cc]           = acc[mt][nt][0];
                out[(size_t)r0 * 128 + cc + 1]       = acc[mt][nt][1];
                out[(size_t)(r0 + 8) * 128 + cc]     = acc[mt][nt][2];
                out[(size_t)(r0 + 8) * 128 + cc + 1] = acc[mt][nt][3];
            }
        }
    }
}

__global__ void sigmoid_comb(const float* __restrict__ pp,
                             const float* __restrict__ bp,
                             float* __restrict__ paths) {
    int tok = blockIdx.x, c = threadIdx.x;   // 64 threads
    if (c < Hh * DEPTH) {
        float z = bp[c];
        #pragma unroll
        for (int s = 0; s < 4; s++)
            z += pp[(size_t)s * NTOK * 128 + (size_t)tok * 128 + c];
        paths[(size_t)tok * (Hh*DEPTH) + c] = 1.f / (1.f + expf(-z));
    }
}

// ---------------- staging / small kernels ----------------
__global__ __launch_bounds__(256) void split_copy(const float4* __restrict__ src,
                                                  float4* __restrict__ hi,
                                                  float4* __restrict__ lo, int n4) {
    int i = blockIdx.x * 256 + threadIdx.x;
    if (i < n4) {
        float4 v = src[i];
        float4 h = make_float4(rnaf(v.x), rnaf(v.y), rnaf(v.z), rnaf(v.w));
        hi[i] = h;
        lo[i] = make_float4(rnaf(v.x - h.x), rnaf(v.y - h.y), rnaf(v.z - h.z), rnaf(v.w - h.w));
    }
}
__global__ __launch_bounds__(256) void round_copy(const float4* __restrict__ src,
                                                  float4* __restrict__ dst, int n4) {
    int i = blockIdx.x * 256 + threadIdx.x;
    if (i < n4) {
        float4 v = src[i];
        dst[i] = make_float4(rnaf(v.x), rnaf(v.y), rnaf(v.z), rnaf(v.w));
    }
}
__global__ __launch_bounds__(256) void wp_prep(const float* __restrict__ Wp) {
    int i = blockIdx.x * 256 + threadIdx.x;   // Dd*128 elements
    if (i < Dd * 128) {
        int k = i >> 7, n = i & 127;
        float h = 0.f, l = 0.f;
        if (n < Hh * DEPTH) {
            float w = Wp[(size_t)k * (Hh * DEPTH) + n];
            h = rnaf(w);
            l = rnaf(w - h);
        }
        g_wph[i] = h;
        g_wpl[i] = l;
    }
}
__global__ __launch_bounds__(256) void zero_k(float4* __restrict__ p, int n4) {
    int i = blockIdx.x * 256 + threadIdx.x;
    if (i < n4) p[i] = make_float4(0.f, 0.f, 0.f, 0.f);
}
__global__ __launch_bounds__(256) void ctx_combine(float4* __restrict__ a,
                                                   const float4* __restrict__ b, int n4) {
    int i = blockIdx.x * 256 + threadIdx.x;
    if (i < n4) {
        float4 x = a[i], y = b[i];
        a[i] = make_float4(rnaf(x.x + y.x), rnaf(x.y + y.y),
                           rnaf(x.z + y.z), rnaf(x.w + y.w));
    }
}

// ---------------- attn: p-adic sim + causal softmax (single pass) ----------
__device__ __forceinline__ float expap(float x) {   // e^x, x in (0,1], deg-7
    float p = 1.98412698e-4f;
    p = fmaf(p, x, 1.38888889e-3f);
    p = fmaf(p, x, 8.33333333e-3f);
    p = fmaf(p, x, 4.16666667e-2f);
    p = fmaf(p, x, 1.66666667e-1f);
    p = fmaf(p, x, 0.5f);
    p = fmaf(p, x, 1.0f);
    p = fmaf(p, x, 1.0f);
    return p;
}

__device__ __forceinline__ float simv(const float* pks, int k,
                                      float p0, float p1, float p2, float p3, float p4,
                                      float o0, float o1, float o2, float o3, float o4) {
    float k0 = pks[k*5+0], k1 = pks[k*5+1], k2 = pks[k*5+2], k3 = pks[k*5+3], k4 = pks[k*5+4];
    float prod = p0 * k0 + o0 * (1.f - k0);
    float s = prod;
    prod *= p1 * k1 + o1 * (1.f - k1); s += prod;
    prod *= p2 * k2 + o2 * (1.f - k2); s += prod;
    prod *= p3 * k3 + o3 * (1.f - k3); s += prod;
    prod *= p4 * k4 + o4 * (1.f - k4); s += prod;
    return s;
}

__global__ __launch_bounds__(256) void attn3_kernel(const float* __restrict__ paths,
                                                    float* __restrict__ attn) {
    __shared__ float pks[Tt * DEPTH];
    int qt = blockIdx.x, h = blockIdx.y, b = blockIdx.z;
    int tid = threadIdx.x;
    int kload = (qt + 1) * 64;
    const float* pb = paths + (size_t)b * Tt * (Hh*DEPTH) + h * DEPTH;
    for (int idx = tid; idx < kload * DEPTH; idx += 256) {
        int k = idx / DEPTH, d = idx - k * DEPTH;
        pks[idx] = pb[(size_t)k * (Hh*DEPTH) + d];
    }
    __syncthreads();

    int warp = tid >> 5, lane = tid & 31;
    float* abase = attn + (size_t)((b * Hh + h) * Tt) * Tt;

    for (int r = 0; r < 8; r++) {
        int q = qt * 64 + r * 8 + warp;
        float p0 = pks[q*5+0], p1 = pks[q*5+1], p2 = pks[q*5+2],
              p3 = pks[q*5+3], p4 = pks[q*5+4];
        float o0 = 1.f - p0, o1 = 1.f - p1, o2 = 1.f - p2, o3 = 1.f - p3, o4 = 1.f - p4;
        int nit = ((q >> 7) + 1) << 2;   // iterations to 128-aligned causal boundary

        float e[32];
        float sum = 0.f;
        #pragma unroll
        for (int i = 0; i < 32; i++) {
            int k = lane + i * 32;
            float ev = 0.f;
            if (i < nit && k <= q)
                ev = expap(simv(pks, k, p0,p1,p2,p3,p4, o0,o1,o2,o3,o4) * 0.2f);
            e[i] = ev;
            sum += ev;
        }
        #pragma unroll
        for (int o = 16; o > 0; o >>= 1) sum += __shfl_xor_sync(0xffffffffu, sum, o);
        float inv = 1.f / sum;

        float* row = abase + (size_t)q * Tt;
        #pragma unroll
        for (int i = 0; i < 32; i++) {
            if (i < nit) row[lane + i * 32] = rnaf(e[i] * inv);
        }
    }
}

// ---------------------------------------------------------------------------
extern "C" void kernel_launch(void* const* d_in, const int* in_sizes, int n_in,
                              void* d_out, int out_size) {
    const float* x  = (const float*)d_in[0];
    const float* Wp = (const float*)d_in[1];
    const float* bp = (const float*)d_in[2];
    const float* Wv = (const float*)d_in[3];
    const float* Wo = (const float*)d_in[4];
    float* out = (float*)d_out;

    float *paths, *xr, *xlo, *wph, *wpl, *pp, *wvr, *wor, *v, *attn, *ctx, *ctx2;
    cudaGetSymbolAddress((void**)&paths, g_paths);
    cudaGetSymbolAddress((void**)&xr,    g_xr);
    cudaGetSymbolAddress((void**)&xlo,   g_xlo);
    cudaGetSymbolAddress((void**)&wph,   g_wph);
    cudaGetSymbolAddress((void**)&wpl,   g_wpl);
    cudaGetSymbolAddress((void**)&pp,    g_pp);
    cudaGetSymbolAddress((void**)&wvr,   g_wvr);
    cudaGetSymbolAddress((void**)&wor,   g_wor);
    cudaGetSymbolAddress((void**)&v,     g_v);
    cudaGetSymbolAddress((void**)&attn,  g_attn);
    cudaGetSymbolAddress((void**)&ctx,   g_ctx);
    cudaGetSymbolAddress((void**)&ctx2,  g_ctx2);

    cudaFuncSetAttribute(gemm_mma,   cudaFuncAttributeMaxDynamicSharedMemorySize, SMEM_GEMM);
    cudaFuncSetAttribute(av_mma,     cudaFuncAttributeMaxDynamicSharedMemorySize, SMEM_GEMM);
    cudaFuncSetAttribute(paths_gemm, cudaFuncAttributeMaxDynamicSharedMemorySize, SMEM_PATHS);

    // staging
    split_copy<<<(NTOK*Dd/4 + 255)/256, 256>>>((const float4*)x, (float4*)xr, (float4*)xlo, NTOK*Dd/4);
    round_copy<<<(Dd*Dd/4 + 255)/256, 256>>>((const float4*)Wv, (float4*)wvr, Dd*Dd/4);
    round_copy<<<(Dd*Dd/4 + 255)/256, 256>>>((const float4*)Wo, (float4*)wor, Dd*Dd/4);
    wp_prep<<<(Dd*128 + 255)/256, 256>>>(Wp);
    zero_k<<<(NTOK*Dd/4 + 255)/256, 256>>>((float4*)ctx2, NTOK*Dd/4);

    // paths = sigmoid(x @ Wp + bp): split-tf32, split-K x4 + combine
    paths_gemm<<<dim3(NTOK/64, 4), 256, SMEM_PATHS>>>(xr, xlo, wph, wpl, pp);
    sigmoid_comb<<<NTOK, 64>>>(pp, bp, paths);

    // V = x @ Wv (rounded store)
    gemm_mma<<<dim3(Dd/128, NTOK/64), 256, SMEM_GEMM>>>(xr, wvr, v, Dd, Dd, 1);

    attn3_kernel<<<dim3(Tt/64, Hh, Bb), 256>>>(paths, attn);

    // ctx = attn @ V, balanced jobs; halves combined + rounded
    av_mma<<<dim3(26, Bb*Hh), 256, SMEM_GEMM>>>(attn, v, ctx, ctx2);
    ctx_combine<<<(NTOK*Dd/4 + 255)/256, 256>>>((float4*)ctx, (const float4*)ctx2, NTOK*Dd/4);

    // out = ctx @ Wo
    gemm_mma<<<dim3(Dd/128, NTOK/64), 256, SMEM_GEMM>>>(ctx, wor, out, Dd, Dd, 0);
}

// round 7
// speedup vs baseline: 4.6129x; 1.1707x over previous
#include <cuda_runtime.h>
#include <math.h>
#include <stdint.h>

#define Bb 2
#define Tt 1024
#define Dd 1024
#define Hh 8
#define DEPTH 5
#define NTOK (Bb*Tt)

// ---------------- scratch (device globals; allocation-free) ----------------
__device__ float g_paths[NTOK*Hh*DEPTH];      // [token][h*5+d]
__device__ float g_xr[NTOK*Dd];               // tf32(rna) hi part of x
__device__ float g_xlo[NTOK*Dd];              // tf32 lo residual of x
__device__ float g_wph[Dd*128];               // Wp hi, padded [k][128]
__device__ float g_wpl[Dd*128];               // Wp lo, padded [k][128]
__device__ float g_pp[4*NTOK*128];            // paths split-K partial logits
__device__ float g_wvr[Dd*Dd];                // rounded Wv [k][n]
__device__ float g_wor[Dd*Dd];                // rounded Wo [k][n]
__device__ float g_v[NTOK*Dd];                // V = x@Wv, rounded
__device__ float g_ctx[NTOK*Dd];              // unnormalized ctx partial (slot 0)
__device__ float g_ctx2[NTOK*Dd];             // unnormalized ctx partial (slot 1)
__device__ float g_rs[2*Bb*Hh*Tt];            // row sums [slot][bh][t]

// av jobs (24/bh, longest first). qt<8 full; qt>=8 split into two K halves.
__constant__ int c_qt[24] = {15,15,14,14,13,13,12,12,11,11,10,10, 9, 9, 8, 8, 7, 6, 5, 4, 3, 2, 1, 0};
__constant__ int c_k0[24] = { 0,16, 0,15, 0,14, 0,13, 0,12, 0,11, 0,10, 0, 9, 0, 0, 0, 0, 0, 0, 0, 0};
__constant__ int c_kt[24] = {16,16,15,15,14,14,13,13,12,12,11,11,10,10, 9, 9,16,14,12,10, 8, 6, 4, 2};
__constant__ int c_ds[24] = { 0, 1, 0, 1, 0, 1, 0, 1, 0, 1, 0, 1, 0, 1, 0, 1, 0, 0, 0, 0, 0, 0, 0, 0};

// ---------------- helpers ----------------
__device__ __forceinline__ float rnaf(float f) {
    uint32_t r; asm("cvt.rna.tf32.f32 %0, %1;" : "=r"(r) : "f"(f));
    return __uint_as_float(r);
}
__device__ __forceinline__ uint32_t smem_u32(const void* p) {
    uint32_t a;
    asm("{ .reg .u64 t; cvta.to.shared.u64 t, %1; cvt.u32.u64 %0, t; }" : "=r"(a) : "l"(p));
    return a;
}
__device__ __forceinline__ void cp16(uint32_t dst, const void* src) {
    asm volatile("cp.async.cg.shared.global [%0], [%1], 16;" :: "r"(dst), "l"(src));
}
__device__ __forceinline__ void mma_tf32(float c[4],
                                         uint32_t a0, uint32_t a1, uint32_t a2, uint32_t a3,
                                         uint32_t b0, uint32_t b1) {
    asm volatile("mma.sync.aligned.m16n8k8.row.col.f32.tf32.tf32.f32 "
                 "{%0,%1,%2,%3}, {%4,%5,%6,%7}, {%8,%9}, {%0,%1,%2,%3};"
                 : "+f"(c[0]), "+f"(c[1]), "+f"(c[2]), "+f"(c[3])
                 : "r"(a0), "r"(a1), "r"(a2), "r"(a3), "r"(b0), "r"(b1));
}
__device__ __forceinline__ float expap(float x) {   // e^x, x in (0,1], deg-7
    float p = 1.98412698e-4f;
    p = fmaf(p, x, 1.38888889e-3f);
    p = fmaf(p, x, 8.33333333e-3f);
    p = fmaf(p, x, 4.16666667e-2f);
    p = fmaf(p, x, 1.66666667e-1f);
    p = fmaf(p, x, 0.5f);
    p = fmaf(p, x, 1.0f);
    p = fmaf(p, x, 1.0f);
    return p;
}

// ---------------------------------------------------------------------------
// dense tf32 GEMM core: C[64,128] tile, 8 warps, BK=32, 3-stage cp.async.
// ---------------------------------------------------------------------------
#define ASTRIDE 36
#define BSTRIDE 136
#define AFLOATS (64*ASTRIDE)
#define STAGEF  (AFLOATS + 32*BSTRIDE)
#define SMEM_GEMM (3*STAGEF*4)

__device__ __forceinline__ void load_stage(uint32_t sb, int s,
                                           const float* A, int lda, int bm,
                                           const float* B, int ldb, int bn,
                                           int tid, int kt) {
    uint32_t sa = sb + s * (STAGEF * 4);
    uint32_t sB = sa + AFLOATS * 4;
    int k0 = kt * 32;
    #pragma unroll
    for (int t = 0; t < 2; t++) {
        int c = tid + t * 256;
        int row = c >> 3, col = c & 7;
        cp16(sa + row * (ASTRIDE*4) + col * 16,
             A + (size_t)(bm + row) * lda + k0 + col * 4);
    }
    #pragma unroll
    for (int t = 0; t < 4; t++) {
        int c = tid + t * 256;
        int row = c >> 5, col = c & 31;
        cp16(sB + row * (BSTRIDE*4) + col * 16,
             B + (size_t)(k0 + row) * ldb + bn + col * 4);
    }
}

__device__ void gemm_core(const float* __restrict__ A, int lda,
                          const float* __restrict__ B, int ldb,
                          float* __restrict__ C, int ldc,
                          int bm, int bn, int KT, int mode) {
    extern __shared__ float sm[];
    uint32_t sb = smem_u32(sm);
    int tid = threadIdx.x;
    int warp = tid >> 5, lane = tid & 31;
    int wm = (warp & 1) * 32;
    int wn = (warp >> 1) * 32;
    int tg = lane >> 2, tk = lane & 3;

    float acc[2][4][4];
    #pragma unroll
    for (int mt = 0; mt < 2; mt++)
        #pragma unroll
        for (int nt = 0; nt < 4; nt++)
            #pragma unroll
            for (int i = 0; i < 4; i++) acc[mt][nt][i] = 0.f;

    load_stage(sb, 0, A, lda, bm, B, ldb, bn, tid, 0);
    asm volatile("cp.async.commit_group;" ::: "memory");
    load_stage(sb, 1, A, lda, bm, B, ldb, bn, tid, 1);
    asm volatile("cp.async.commit_group;" ::: "memory");

    for (int it = 0; it < KT; it++) {
        asm volatile("cp.async.wait_group 1;" ::: "memory");
        __syncthreads();
        int pf = it + 2;
        if (pf < KT) load_stage(sb, pf % 3, A, lda, bm, B, ldb, bn, tid, pf);
        asm volatile("cp.async.commit_group;" ::: "memory");

        const float* As = sm + (it % 3) * STAGEF;
        const float* Bs = As + AFLOATS;
        #pragma unroll
        for (int kq = 0; kq < 32; kq += 8) {
            uint32_t af[2][4], bf[4][2];
            #pragma unroll
            for (int mt = 0; mt < 2; mt++) {
                int m = wm + mt * 16 + tg;
                af[mt][0] = __float_as_uint(As[m * ASTRIDE + kq + tk]);
                af[mt][1] = __float_as_uint(As[(m + 8) * ASTRIDE + kq + tk]);
                af[mt][2] = __float_as_uint(As[m * ASTRIDE + kq + tk + 4]);
                af[mt][3] = __float_as_uint(As[(m + 8) * ASTRIDE + kq + tk + 4]);
            }
            #pragma unroll
            for (int nt = 0; nt < 4; nt++) {
                int n = wn + nt * 8 + tg;
                bf[nt][0] = __float_as_uint(Bs[(kq + tk) * BSTRIDE + n]);
                bf[nt][1] = __float_as_uint(Bs[(kq + tk + 4) * BSTRIDE + n]);
            }
            #pragma unroll
            for (int mt = 0; mt < 2; mt++)
                #pragma unroll
                for (int nt = 0; nt < 4; nt++)
                    mma_tf32(acc[mt][nt], af[mt][0], af[mt][1], af[mt][2], af[mt][3],
                             bf[nt][0], bf[nt][1]);
        }
        __syncthreads();
    }

    #pragma unroll
    for (int mt = 0; mt < 2; mt++) {
        #pragma unroll
        for (int nt = 0; nt < 4; nt++) {
            int r0 = bm + wm + mt * 16 + tg;
            int cc = bn + wn + nt * 8 + tk * 2;
            float2 v0 = make_float2(acc[mt][nt][0], acc[mt][nt][1]);
            float2 v1 = make_float2(acc[mt][nt][2], acc[mt][nt][3]);
            if (mode == 1) {
                v0.x = rnaf(v0.x); v0.y = rnaf(v0.y);
                v1.x = rnaf(v1.x); v1.y = rnaf(v1.y);
            }
            *(float2*)&C[(size_t)r0 * ldc + cc]       = v0;
            *(float2*)&C[(size_t)(r0 + 8) * ldc + cc] = v1;
        }
    }
}

__global__ __launch_bounds__(256) void gemm_mma(const float* __restrict__ A,
                                                const float* __restrict__ Bw,
                                                float* __restrict__ C,
                                                int K, int N, int mode) {
    gemm_core(A, K, Bw, N, C, N, blockIdx.y * 64, blockIdx.x * 128, K / 32, mode);
}

// ---------------------------------------------------------------------------
// Fused av: per K-tile, compute the 64x32 e = exp(sim/5) tile in-kernel
// (FMA pipe, hidden under MMA), accumulate unnormalized ctx and rowsums.
// smem (floats): As 64*36 | Bs 3*32*136 | pqs 320 | pks 160
// ---------------------------------------------------------------------------
#define AV_AS     0
#define AV_BS     (64*ASTRIDE)
#define AV_PQ     (AV_BS + 3*32*BSTRIDE)
#define AV_PK     (AV_PQ + 320)
#define AV_FLOATS (AV_PK + 160)
#define SMEM_AV   (AV_FLOATS*4)

__global__ __launch_bounds__(256) void av_fused(const float* __restrict__ paths,
                                                const float* __restrict__ v,
                                                float* __restrict__ ctx,
                                                float* __restrict__ ctx2,
                                                float* __restrict__ rs) {
    extern __shared__ float sm[];
    uint32_t sb = smem_u32(sm);
    int j = blockIdx.x, bh = blockIdx.y;
    int qt = c_qt[j], k0t = c_k0[j], KT = c_kt[j], ds = c_ds[j];
    int b = bh >> 3, h = bh & 7;
    int tid = threadIdx.x;
    int warp = tid >> 5, lane = tid & 31;

    const float* pb = paths + (size_t)(b * Tt) * (Hh*DEPTH) + h * DEPTH;
    const float* Bv = v + (size_t)b * Tt * Dd + h * 128;
    float* As  = sm + AV_AS;
    float* pqs = sm + AV_PQ;
    float* pks = sm + AV_PK;

    // q-tile paths -> smem (once)
    for (int idx = tid; idx < 64 * DEPTH; idx += 256)
        pqs[idx] = pb[(size_t)(qt * 64 + idx / DEPTH) * (Hh*DEPTH) + idx % DEPTH];

    // prefetch V stages 0,1
    {
        uint32_t sB = sb + AV_BS * 4;
        #pragma unroll
        for (int s = 0; s < 2; s++) {
            int kb = (k0t + s) * 32;
            #pragma unroll
            for (int t = 0; t < 4; t++) {
                int c = tid + t * 256;
                int row = c >> 5, col = c & 31;
                cp16(sB + s * (32*BSTRIDE*4) + row * (BSTRIDE*4) + col * 16,
                     Bv + (size_t)(kb + row) * Dd + col * 4);
            }
            asm volatile("cp.async.commit_group;" ::: "memory");
        }
    }

    int wm = (warp & 1) * 32;
    int wn = (warp >> 1) * 32;
    int tg = lane >> 2, tk = lane & 3;
    float acc[2][4][4];
    #pragma unroll
    for (int mt = 0; mt < 2; mt++)
        #pragma unroll
        for (int nt = 0; nt < 4; nt++)
            #pragma unroll
            for (int i = 0; i < 4; i++) acc[mt][nt][i] = 0.f;
    float rsum[8];
    #pragma unroll
    for (int i = 0; i < 8; i++) rsum[i] = 0.f;

    for (int it = 0; it < KT; it++) {
        int kb = (k0t + it) * 32;
        // (A) k-tile paths -> smem
        if (tid < 32 * DEPTH)
            pks[tid] = pb[(size_t)(kb + tid / DEPTH) * (Hh*DEPTH) + tid % DEPTH];
        __syncthreads();   // pks visible; prev iter MMA done reading As

        // (B) e-tile: thread -> (rows warp*8..+7, k = lane)
        {
            float k0v = pks[lane*5+0], k1v = pks[lane*5+1], k2v = pks[lane*5+2],
                  k3v = pks[lane*5+3], k4v = pks[lane*5+4];
            float m0 = 1.f - k0v, m1 = 1.f - k1v, m2 = 1.f - k2v,
                  m3 = 1.f - k3v, m4 = 1.f - k4v;
            int kglob = kb + lane;
            #pragma unroll
            for (int jr = 0; jr < 8; jr++) {
                int row = warp * 8 + jr;
                const float* pq = pqs + row * 5;
                float p0 = pq[0], p1 = pq[1], p2 = pq[2], p3 = pq[3], p4 = pq[4];
                float prod = p0 * k0v + (1.f - p0) * m0;
                float s = prod;
                prod *= p1 * k1v + (1.f - p1) * m1; s += prod;
                prod *= p2 * k2v + (1.f - p2) * m2; s += prod;
                prod *= p3 * k3v + (1.f - p3) * m3; s += prod;
                prod *= p4 * k4v + (1.f - p4) * m4; s += prod;
                float ev = 0.f;
                if (kglob <= qt * 64 + row) ev = rnaf(expap(s * 0.2f));
                rsum[jr] += ev;
                As[row * ASTRIDE + lane] = ev;
            }
        }

        asm volatile("cp.async.wait_group 1;" ::: "memory");
        __syncthreads();   // As + V stage ready

        // prefetch V stage it+2
        int pf = it + 2;
        if (pf < KT) {
            uint32_t sB = sb + AV_BS * 4 + (pf % 3) * (32*BSTRIDE*4);
            int kb2 = (k0t + pf) * 32;
            #pragma unroll
            for (int t = 0; t < 4; t++) {
                int c = tid + t * 256;
                int row = c >> 5, col = c & 31;
                cp16(sB + row * (BSTRIDE*4) + col * 16,
                     Bv + (size_t)(kb2 + row) * Dd + col * 4);
            }
        }
        asm volatile("cp.async.commit_group;" ::: "memory");

        // (C) MMA
        const float* Bs = sm + AV_BS + (it % 3) * (32*BSTRIDE);
        #pragma unroll
        for (int kq = 0; kq < 32; kq += 8) {
            uint32_t af[2][4], bf[4][2];
            #pragma unroll
            for (int mt = 0; mt < 2; mt++) {
                int m = wm + mt * 16 + tg;
                af[mt][0] = __float_as_uint(As[m * ASTRIDE + kq + tk]);
                af[mt][1] = __float_as_uint(As[(m + 8) * ASTRIDE + kq + tk]);
                af[mt][2] = __float_as_uint(As[m * ASTRIDE + kq + tk + 4]);
                af[mt][3] = __float_as_uint(As[(m + 8) * ASTRIDE + kq + tk + 4]);
            }
            #pragma unroll
            for (int nt = 0; nt < 4; nt++) {
                int n = wn + nt * 8 + tg;
                bf[nt][0] = __float_as_uint(Bs[(kq + tk) * BSTRIDE + n]);
                bf[nt][1] = __float_as_uint(Bs[(kq + tk + 4) * BSTRIDE + n]);
            }
            #pragma unroll
            for (int mt = 0; mt < 2; mt++)
                #pragma unroll
                for (int nt = 0; nt < 4; nt++)
                    mma_tf32(acc[mt][nt], af[mt][0], af[mt][1], af[mt][2], af[mt][3],
                             bf[nt][0], bf[nt][1]);
        }
    }

    // rowsums
    float* rsp = rs + (size_t)ds * (Bb*Hh) * Tt + (size_t)bh * Tt + qt * 64;
    #pragma unroll
    for (int jr = 0; jr < 8; jr++) {
        float s = rsum[jr];
        #pragma unroll
        for (int o = 16; o > 0; o >>= 1) s += __shfl_xor_sync(0xffffffffu, s, o);
        if (lane == 0) rsp[warp * 8 + jr] = s;
    }

    // unnormalized ctx store
    float* C = (ds ? ctx2 : ctx) + (size_t)b * Tt * Dd + h * 128;
    #pragma unroll
    for (int mt = 0; mt < 2; mt++) {
        #pragma unroll
        for (int nt = 0; nt < 4; nt++) {
            int r0 = qt * 64 + wm + mt * 16 + tg;
            int cc = wn + nt * 8 + tk * 2;
            *(float2*)&C[(size_t)r0 * Dd + cc]       = make_float2(acc[mt][nt][0], acc[mt][nt][1]);
            *(float2*)&C[(size_t)(r0 + 8) * Dd + cc] = make_float2(acc[mt][nt][2], acc[mt][nt][3]);
        }
    }
}

// normalize + combine: ctx = rna((c1+c2)/(r1+r2))
__global__ __launch_bounds__(256) void ctx_norm(float4* __restrict__ ctx,
                                                const float4* __restrict__ ctx2,
                                                const float* __restrict__ rs) {
    int i = blockIdx.x * 256 + threadIdx.x;
    if (i < NTOK * Dd / 4) {
        int r = i / (Dd / 4);
        int c4 = i % (Dd / 4);
        int bh = (r >> 10) * 8 + (c4 >> 5);
        int t = r & 1023;
        float denom = rs[(size_t)bh * Tt + t] + rs[(size_t)(Bb*Hh) * Tt + (size_t)bh * Tt + t];
        float inv = 1.f / denom;
        float4 xa = ctx[i], xb = ctx2[i];
        ctx[i] = make_float4(rnaf((xa.x + xb.x) * inv), rnaf((xa.y + xb.y) * inv),
                             rnaf((xa.z + xb.z) * inv), rnaf((xa.w + xb.w) * inv));
    }
}

// zero slot-1 buffers for unsplit rows (t < 512 per batch)
__global__ __launch_bounds__(256) void zero_parts(float4* __restrict__ ctx2,
                                                  float* __restrict__ rs) {
    int i = blockIdx.x * 256 + threadIdx.x;
    const int n_ctx4 = Bb * 512 * Dd / 4;
    if (i < n_ctx4) {
        int b = i / (512 * Dd / 4);
        int off = i % (512 * Dd / 4);
        ctx2[(size_t)b * Tt * Dd / 4 + off] = make_float4(0.f, 0.f, 0.f, 0.f);
    }
    int jx = i - n_ctx4;
    if (jx >= 0 && jx < Bb*Hh*512) {
        int bh = jx / 512, t = jx % 512;
        rs[(size_t)(Bb*Hh) * Tt + (size_t)bh * Tt + t] = 0.f;
    }
}

// ---------------------------------------------------------------------------
// paths GEMM split-K x4 (split-tf32, 3 mma) + combine (unchanged from R6)
// ---------------------------------------------------------------------------
#define PSTAGEF (2*64*36 + 2*32*136)
#define SMEM_PATHS (2*PSTAGEF*4)

__device__ __forceinline__ void paths_load(uint32_t sb, int s,
                                           const float* xh, const float* xl, int bm,
                                           const float* wh, const float* wl,
                                           int tid, int kt) {
    uint32_t base = sb + s * (PSTAGEF * 4);
    uint32_t xh_o = base;
    uint32_t xl_o = base + 64*36*4;
    uint32_t wh_o = xl_o + 64*36*4;
    uint32_t wl_o = wh_o + 32*136*4;
    int k0 = kt * 32;
    #pragma unroll
    for (int t = 0; t < 2; t++) {
        int c = tid + t * 256;
        int row = c >> 3, col = c & 7;
        size_t go = (size_t)(bm + row) * Dd + k0 + col * 4;
        uint32_t so = row * (36*4) + col * 16;
        cp16(xh_o + so, xh + go);
        cp16(xl_o + so, xl + go);
    }
    #pragma unroll
    for (int t = 0; t < 4; t++) {
        int c = tid + t * 256;
        int row = c >> 5, col = c & 31;
        size_t go = (size_t)(k0 + row) * 128 + col * 4;
        uint32_t so = row * (136*4) + col * 16;
        cp16(wh_o + so, wh + go);
        cp16(wl_o + so, wl + go);
    }
}

__global__ __launch_bounds__(256) void paths_gemm(const float* __restrict__ xh0,
                                                  const float* __restrict__ xl0,
                                                  const float* __restrict__ wh0,
                                                  const float* __restrict__ wl0,
                                                  float* __restrict__ pp) {
    extern __shared__ float sm[];
    uint32_t sb = smem_u32(sm);
    int tid = threadIdx.x;
    int warp = tid >> 5, lane = tid & 31;
    int wm = (warp & 1) * 32;
    int wn = (warp >> 1) * 32;
    int tg = lane >> 2, tk = lane & 3;
    int bm = blockIdx.x * 64;
    int sp = blockIdx.y;
    const float* xh = xh0 + sp * 256;
    const float* xl = xl0 + sp * 256;
    const float* wh = wh0 + (size_t)(sp * 256) * 128;
    const float* wl = wl0 + (size_t)(sp * 256) * 128;
    float* out = pp + (size_t)sp * NTOK * 128;
    const int KT = 8;

    float acc[2][4][4];
    #pragma unroll
    for (int mt = 0; mt < 2; mt++)
        #pragma unroll
        for (int nt = 0; nt < 4; nt++)
            #pragma unroll
            for (int i = 0; i < 4; i++) acc[mt][nt][i] = 0.f;

    paths_load(sb, 0, xh, xl, bm, wh, wl, tid, 0);
    asm volatile("cp.async.commit_group;" ::: "memory");

    for (int it = 0; it < KT; it++) {
        int pf = it + 1;
        if (pf < KT) {
            paths_load(sb, pf & 1, xh, xl, bm, wh, wl, tid, pf);
            asm volatile("cp.async.commit_group;" ::: "memory");
            asm volatile("cp.async.wait_group 1;" ::: "memory");
        } else {
            asm volatile("cp.async.wait_group 0;" ::: "memory");
        }
        __syncthreads();

        const float* Xh = sm + (it & 1) * PSTAGEF;
        const float* Xl = Xh + 64*36;
        const float* Wh = Xl + 64*36;
        const float* Wl = Wh + 32*136;
        #pragma unroll
        for (int kq = 0; kq < 32; kq += 8) {
            uint32_t ah[2][4], al[2][4], bh[4][2], bl[4][2];
            #pragma unroll
            for (int mt = 0; mt < 2; mt++) {
                int m = wm + mt * 16 + tg;
                ah[mt][0] = __float_as_uint(Xh[m * 36 + kq + tk]);
                ah[mt][1] = __float_as_uint(Xh[(m + 8) * 36 + kq + tk]);
                ah[mt][2] = __float_as_uint(Xh[m * 36 + kq + tk + 4]);
                ah[mt][3] = __float_as_uint(Xh[(m + 8) * 36 + kq + tk + 4]);
                al[mt][0] = __float_as_uint(Xl[m * 36 + kq + tk]);
                al[mt][1] = __float_as_uint(Xl[(m + 8) * 36 + kq + tk]);
                al[mt][2] = __float_as_uint(Xl[m * 36 + kq + tk + 4]);
                al[mt][3] = __float_as_uint(Xl[(m + 8) * 36 + kq + tk + 4]);
            }
            #pragma unroll
            for (int nt = 0; nt < 4; nt++) {
                int n = wn + nt * 8 + tg;
                bh[nt][0] = __float_as_uint(Wh[(kq + tk) * 136 + n]);
                bh[nt][1] = __float_as_uint(Wh[(kq + tk + 4) * 136 + n]);
                bl[nt][0] = __float_as_uint(Wl[(kq + tk) * 136 + n]);
                bl[nt][1] = __float_as_uint(Wl[(kq + tk + 4) * 136 + n]);
            }
            #pragma unroll
            for (int mt = 0; mt < 2; mt++)
                #pragma unroll
                for (int nt = 0; nt < 4; nt++) {
                    mma_tf32(acc[mt][nt], ah[mt][0], ah[mt][1], ah[mt][2], ah[mt][3],
                             bh[nt][0], bh[nt][1]);
                    mma_tf32(acc[mt][nt], ah[mt][0], ah[mt][1], ah[mt][2], ah[mt][3],
                             bl[nt][0], bl[nt][1]);
                    mma_tf32(acc[mt][nt], al[mt][0], al[mt][1], al[mt][2], al[mt][3],
                             bh[nt][0], bh[nt][1]);
                }
        }
        __syncthreads();
    }

    #pragma unroll
    for (int mt = 0; mt < 2; mt++) {
        #pragma unroll
        for (int nt = 0; nt < 4; nt++) {
            int cc = wn + nt * 8 + tk * 2;
            if (cc < Hh * DEPTH) {
                int r0 = bm + wm + mt * 16 + tg;
                out[(size_t)r0 * 128 + cc]           = acc[mt][nt][0];
                out[(size_t)r0 * 128 + cc + 1]       = acc[mt][nt][1];
                out[(size_t)(r0 + 8) * 128 + cc]     = acc[mt][nt][2];
                out[(size_t)(r0 + 8) * 128 + cc + 1] = acc[mt][nt][3];
            }
        }
    }
}

__global__ void sigmoid_comb(const float* __restrict__ pp,
                             const float* __restrict__ bp,
                             float* __restrict__ paths) {
    int tok = blockIdx.x, c = threadIdx.x;
    if (c < Hh * DEPTH) {
        float z = bp[c];
        #pragma unroll
        for (int s = 0; s < 4; s++)
            z += pp[(size_t)s * NTOK * 128 + (size_t)tok * 128 + c];
        paths[(size_t)tok * (Hh*DEPTH) + c] = 1.f / (1.f + expf(-z));
    }
}

// ---------------- staging ----------------
__global__ __launch_bounds__(256) void split_copy(const float4* __restrict__ src,
                                                  float4* __restrict__ hi,
                                                  float4* __restrict__ lo, int n4) {
    int i = blockIdx.x * 256 + threadIdx.x;
    if (i < n4) {
        float4 v = src[i];
        float4 h = make_float4(rnaf(v.x), rnaf(v.y), rnaf(v.z), rnaf(v.w));
        hi[i] = h;
        lo[i] = make_float4(rnaf(v.x - h.x), rnaf(v.y - h.y), rnaf(v.z - h.z), rnaf(v.w - h.w));
    }
}
__global__ __launch_bounds__(256) void round2_copy(const float4* __restrict__ s1,
                                                   float4* __restrict__ d1,
                                                   const float4* __restrict__ s2,
                                                   float4* __restrict__ d2, int n4) {
    int i = blockIdx.x * 256 + threadIdx.x;
    if (i < n4) {
        float4 a = s1[i], b = s2[i];
        d1[i] = make_float4(rnaf(a.x), rnaf(a.y), rnaf(a.z), rnaf(a.w));
        d2[i] = make_float4(rnaf(b.x), rnaf(b.y), rnaf(b.z), rnaf(b.w));
    }
}
__global__ __launch_bounds__(256) void wp_prep(const float* __restrict__ Wp) {
    int i = blockIdx.x * 256 + threadIdx.x;
    if (i < Dd * 128) {
        int k = i >> 7, n = i & 127;
        float h = 0.f, l = 0.f;
        if (n < Hh * DEPTH) {
            float w = Wp[(size_t)k * (Hh * DEPTH) + n];
            h = rnaf(w);
            l = rnaf(w - h);
        }
        g_wph[i] = h;
        g_wpl[i] = l;
    }
}

// ---------------------------------------------------------------------------
extern "C" void kernel_launch(void* const* d_in, const int* in_sizes, int n_in,
                              void* d_out, int out_size) {
    const float* x  = (const float*)d_in[0];
    const float* Wp = (const float*)d_in[1];
    const float* bp = (const float*)d_in[2];
    const float* Wv = (const float*)d_in[3];
    const float* Wo = (const float*)d_in[4];
    float* out = (float*)d_out;

    float *paths, *xr, *xlo, *wph, *wpl, *pp, *wvr, *wor, *v, *ctx, *ctx2, *rs;
    cudaGetSymbolAddress((void**)&paths, g_paths);
    cudaGetSymbolAddress((void**)&xr,    g_xr);
    cudaGetSymbolAddress((void**)&xlo,   g_xlo);
    cudaGetSymbolAddress((void**)&wph,   g_wph);
    cudaGetSymbolAddress((void**)&wpl,   g_wpl);
    cudaGetSymbolAddress((void**)&pp,    g_pp);
    cudaGetSymbolAddress((void**)&wvr,   g_wvr);
    cudaGetSymbolAddress((void**)&wor,   g_wor);
    cudaGetSymbolAddress((void**)&v,     g_v);
    cudaGetSymbolAddress((void**)&ctx,   g_ctx);
    cudaGetSymbolAddress((void**)&ctx2,  g_ctx2);
    cudaGetSymbolAddress((void**)&rs,    g_rs);

    cudaFuncSetAttribute(gemm_mma,   cudaFuncAttributeMaxDynamicSharedMemorySize, SMEM_GEMM);
    cudaFuncSetAttribute(av_fused,   cudaFuncAttributeMaxDynamicSharedMemorySize, SMEM_AV);
    cudaFuncSetAttribute(paths_gemm, cudaFuncAttributeMaxDynamicSharedMemorySize, SMEM_PATHS);

    // staging
    split_copy<<<(NTOK*Dd/4 + 255)/256, 256>>>((const float4*)x, (float4*)xr, (float4*)xlo, NTOK*Dd/4);
    round2_copy<<<(Dd*Dd/4 + 255)/256, 256>>>((const float4*)Wv, (float4*)wvr,
                                              (const float4*)Wo, (float4*)wor, Dd*Dd/4);
    wp_prep<<<(Dd*128 + 255)/256, 256>>>(Wp);
    zero_parts<<<(Bb*512*Dd/4 + Bb*Hh*512 + 255)/256, 256>>>((float4*)ctx2, rs);

    // paths = sigmoid(x @ Wp + bp)
    paths_gemm<<<dim3(NTOK/64, 4), 256, SMEM_PATHS>>>(xr, xlo, wph, wpl, pp);
    sigmoid_comb<<<NTOK, 64>>>(pp, bp, paths);

    // V = x @ Wv (rounded store)
    gemm_mma<<<dim3(Dd/128, NTOK/64), 256, SMEM_GEMM>>>(xr, wvr, v, Dd, Dd, 1);

    // fused sim+softmax+attn@V (unnormalized) + rowsums
    av_fused<<<dim3(24, Bb*Hh), 256, SMEM_AV>>>(paths, v, ctx, ctx2, rs);

    // normalize + combine halves
    ctx_norm<<<(NTOK*Dd/4 + 255)/256, 256>>>((float4*)ctx, (const float4*)ctx2, rs);

    // out = ctx @ Wo
    gemm_mma<<<dim3(Dd/128, NTOK/64), 256, SMEM_GEMM>>>(ctx, wor, out, Dd, Dd, 0);
}

// round 8
// speedup vs baseline: 4.8602x; 1.0536x over previous
#include <cuda_runtime.h>
#include <math.h>
#include <stdint.h>

#define Bb 2
#define Tt 1024
#define Dd 1024
#define Hh 8
#define DEPTH 5
#define NTOK (Bb*Tt)

// ---------------- scratch (device globals; allocation-free) ----------------
__device__ float g_paths[NTOK*Hh*DEPTH];      // [token][h*5+d]
__device__ float g_xr[NTOK*Dd];               // tf32(rna) hi part of x
__device__ float g_xlo[NTOK*Dd];              // tf32 lo residual of x
__device__ float g_wph[Dd*128];               // Wp hi, padded [k][128]
__device__ float g_wpl[Dd*128];               // Wp lo, padded [k][128]
__device__ float g_pp[4*NTOK*128];            // paths split-K partial logits
__device__ float g_wvr[Dd*Dd];                // rounded Wv [k][n]
__device__ float g_wor[Dd*Dd];                // rounded Wo [k][n]
__device__ float g_v[NTOK*Dd];                // V = x@Wv, rounded
__device__ float g_ctx[NTOK*Dd];              // ctx (t<512 final; t>=512 partial slot0)
__device__ float g_ctx2[NTOK*Dd];             // ctx partial slot1 (t>=512 only)
__device__ float g_rs[2*Bb*Hh*Tt];            // row sums [slot][bh][t] (t>=512 only used)

// av jobs (24/bh, longest first). qt<8 full (self-normalized); qt>=8 split.
__constant__ int c_qt[24] = {15,15,14,14,13,13,12,12,11,11,10,10, 9, 9, 8, 8, 7, 6, 5, 4, 3, 2, 1, 0};
__constant__ int c_k0[24] = { 0,16, 0,15, 0,14, 0,13, 0,12, 0,11, 0,10, 0, 9, 0, 0, 0, 0, 0, 0, 0, 0};
__constant__ int c_kt[24] = {16,16,15,15,14,14,13,13,12,12,11,11,10,10, 9, 9,16,14,12,10, 8, 6, 4, 2};
__constant__ int c_ds[24] = { 0, 1, 0, 1, 0, 1, 0, 1, 0, 1, 0, 1, 0, 1, 0, 1, 0, 0, 0, 0, 0, 0, 0, 0};

// ---------------- helpers ----------------
__device__ __forceinline__ float rnaf(float f) {
    uint32_t r; asm("cvt.rna.tf32.f32 %0, %1;" : "=r"(r) : "f"(f));
    return __uint_as_float(r);
}
__device__ __forceinline__ uint32_t smem_u32(const void* p) {
    uint32_t a;
    asm("{ .reg .u64 t; cvta.to.shared.u64 t, %1; cvt.u32.u64 %0, t; }" : "=r"(a) : "l"(p));
    return a;
}
__device__ __forceinline__ void cp16(uint32_t dst, const void* src) {
    asm volatile("cp.async.cg.shared.global [%0], [%1], 16;" :: "r"(dst), "l"(src));
}
__device__ __forceinline__ void mma_tf32(float c[4],
                                         uint32_t a0, uint32_t a1, uint32_t a2, uint32_t a3,
                                         uint32_t b0, uint32_t b1) {
    asm volatile("mma.sync.aligned.m16n8k8.row.col.f32.tf32.tf32.f32 "
                 "{%0,%1,%2,%3}, {%4,%5,%6,%7}, {%8,%9}, {%0,%1,%2,%3};"
                 : "+f"(c[0]), "+f"(c[1]), "+f"(c[2]), "+f"(c[3])
                 : "r"(a0), "r"(a1), "r"(a2), "r"(a3), "r"(b0), "r"(b1));
}
__device__ __forceinline__ float expap(float x) {   // e^x, x in (0,1], deg-7
    float p = 1.98412698e-4f;
    p = fmaf(p, x, 1.38888889e-3f);
    p = fmaf(p, x, 8.33333333e-3f);
    p = fmaf(p, x, 4.16666667e-2f);
    p = fmaf(p, x, 1.66666667e-1f);
    p = fmaf(p, x, 0.5f);
    p = fmaf(p, x, 1.0f);
    p = fmaf(p, x, 1.0f);
    return p;
}

#define ASTRIDE 36
#define BSTRIDE 136

// ---------------------------------------------------------------------------
// dense tf32 GEMM: C[128,128] tile, 8 warps (2x4 of 64x32), BK=32, 3-stage.
// Halves L2 traffic vs 64x128 tiling. 128 CTAs = 1/SM.
// ---------------------------------------------------------------------------
#define A2FLOATS (128*ASTRIDE)                 // 4608
#define STAGEF2  (A2FLOATS + 32*BSTRIDE)       // 8960 floats
#define SMEM_GEMM2 (3*STAGEF2*4)               // 107520 B

__device__ __forceinline__ void load_stage2(uint32_t sb, int s,
                                            const float* A, int lda, int bm,
                                            const float* B, int ldb, int bn,
                                            int tid, int kt) {
    uint32_t sa = sb + s * (STAGEF2 * 4);
    uint32_t sB = sa + A2FLOATS * 4;
    int k0 = kt * 32;
    #pragma unroll
    for (int t = 0; t < 4; t++) {
        int c = tid + t * 256;
        int row = c >> 3, col = c & 7;
        cp16(sa + row * (ASTRIDE*4) + col * 16,
             A + (size_t)(bm + row) * lda + k0 + col * 4);
    }
    #pragma unroll
    for (int t = 0; t < 4; t++) {
        int c = tid + t * 256;
        int row = c >> 5, col = c & 31;
        cp16(sB + row * (BSTRIDE*4) + col * 16,
             B + (size_t)(k0 + row) * ldb + bn + col * 4);
    }
}

__global__ __launch_bounds__(256, 1) void gemm128(const float* __restrict__ A,
                                                  const float* __restrict__ Bw,
                                                  float* __restrict__ C,
                                                  int K, int N, int mode) {
    extern __shared__ float sm[];
    uint32_t sb = smem_u32(sm);
    int tid = threadIdx.x;
    int warp = tid >> 5, lane = tid & 31;
    int wm = (warp & 1) * 64;
    int wn = (warp >> 1) * 32;
    int tg = lane >> 2, tk = lane & 3;
    int bm = blockIdx.y * 128, bn = blockIdx.x * 128;
    int KT = K / 32;

    float acc[4][4][4];
    #pragma unroll
    for (int mt = 0; mt < 4; mt++)
        #pragma unroll
        for (int nt = 0; nt < 4; nt++)
            #pragma unroll
            for (int i = 0; i < 4; i++) acc[mt][nt][i] = 0.f;

    load_stage2(sb, 0, A, K, bm, Bw, N, bn, tid, 0);
    asm volatile("cp.async.commit_group;" ::: "memory");
    load_stage2(sb, 1, A, K, bm, Bw, N, bn, tid, 1);
    asm volatile("cp.async.commit_group;" ::: "memory");

    for (int it = 0; it < KT; it++) {
        asm volatile("cp.async.wait_group 1;" ::: "memory");
        __syncthreads();
        int pf = it + 2;
        if (pf < KT) load_stage2(sb, pf % 3, A, K, bm, Bw, N, bn, tid, pf);
        asm volatile("cp.async.commit_group;" ::: "memory");

        const float* As = sm + (it % 3) * STAGEF2;
        const float* Bs = As + A2FLOATS;
        #pragma unroll
        for (int kq = 0; kq < 32; kq += 8) {
            uint32_t af[4][4], bf[4][2];
            #pragma unroll
            for (int mt = 0; mt < 4; mt++) {
                int m = wm + mt * 16 + tg;
                af[mt][0] = __float_as_uint(As[m * ASTRIDE + kq + tk]);
                af[mt][1] = __float_as_uint(As[(m + 8) * ASTRIDE + kq + tk]);
                af[mt][2] = __float_as_uint(As[m * ASTRIDE + kq + tk + 4]);
                af[mt][3] = __float_as_uint(As[(m + 8) * ASTRIDE + kq + tk + 4]);
            }
            #pragma unroll
            for (int nt = 0; nt < 4; nt++) {
                int n = wn + nt * 8 + tg;
                bf[nt][0] = __float_as_uint(Bs[(kq + tk) * BSTRIDE + n]);
                bf[nt][1] = __float_as_uint(Bs[(kq + tk + 4) * BSTRIDE + n]);
            }
            #pragma unroll
            for (int mt = 0; mt < 4; mt++)
                #pragma unroll
                for (int nt = 0; nt < 4; nt++)
                    mma_tf32(acc[mt][nt], af[mt][0], af[mt][1], af[mt][2], af[mt][3],
                             bf[nt][0], bf[nt][1]);
        }
        __syncthreads();
    }

    #pragma unroll
    for (int mt = 0; mt < 4; mt++) {
        #pragma unroll
        for (int nt = 0; nt < 4; nt++) {
            int r0 = bm + wm + mt * 16 + tg;
            int cc = bn + wn + nt * 8 + tk * 2;
            float2 v0 = make_float2(acc[mt][nt][0], acc[mt][nt][1]);
            float2 v1 = make_float2(acc[mt][nt][2], acc[mt][nt][3]);
            if (mode == 1) {
                v0.x = rnaf(v0.x); v0.y = rnaf(v0.y);
                v1.x = rnaf(v1.x); v1.y = rnaf(v1.y);
            }
            *(float2*)&C[(size_t)r0 * N + cc]       = v0;
            *(float2*)&C[(size_t)(r0 + 8) * N + cc] = v1;
        }
    }
}

// ---------------------------------------------------------------------------
// Fused av (64x128 tiles): e = exp(sim/5) computed on FMA pipe under MMA.
// Unsplit jobs (qt<8) self-normalize via smem rowsum table; split jobs write
// unnormalized partials + rowsums for ctx_norm.
// ---------------------------------------------------------------------------
#define AV_AS     0
#define AV_BS     (64*ASTRIDE)
#define AV_PQ     (AV_BS + 3*32*BSTRIDE)
#define AV_PK     (AV_PQ + 320)
#define AV_RS     (AV_PK + 160)
#define AV_FLOATS (AV_RS + 64)
#define SMEM_AV   (AV_FLOATS*4)

__global__ __launch_bounds__(256) void av_fused(const float* __restrict__ paths,
                                                const float* __restrict__ v,
                                                float* __restrict__ ctx,
                                                float* __restrict__ ctx2,
                                                float* __restrict__ rs) {
    extern __shared__ float sm[];
    uint32_t sb = smem_u32(sm);
    int j = blockIdx.x, bh = blockIdx.y;
    int qt = c_qt[j], k0t = c_k0[j], KT = c_kt[j], ds = c_ds[j];
    int b = bh >> 3, h = bh & 7;
    int tid = threadIdx.x;
    int warp = tid >> 5, lane = tid & 31;

    const float* pb = paths + (size_t)(b * Tt) * (Hh*DEPTH) + h * DEPTH;
    const float* Bv = v + (size_t)b * Tt * Dd + h * 128;
    float* As  = sm + AV_AS;
    float* pqs = sm + AV_PQ;
    float* pks = sm + AV_PK;
    float* rsm = sm + AV_RS;

    for (int idx = tid; idx < 64 * DEPTH; idx += 256)
        pqs[idx] = pb[(size_t)(qt * 64 + idx / DEPTH) * (Hh*DEPTH) + idx % DEPTH];

    {
        uint32_t sB = sb + AV_BS * 4;
        #pragma unroll
        for (int s = 0; s < 2; s++) {
            int kb = (k0t + s) * 32;
            #pragma unroll
            for (int t = 0; t < 4; t++) {
                int c = tid + t * 256;
                int row = c >> 5, col = c & 31;
                cp16(sB + s * (32*BSTRIDE*4) + row * (BSTRIDE*4) + col * 16,
                     Bv + (size_t)(kb + row) * Dd + col * 4);
            }
            asm volatile("cp.async.commit_group;" ::: "memory");
        }
    }

    int wm = (warp & 1) * 32;
    int wn = (warp >> 1) * 32;
    int tg = lane >> 2, tk = lane & 3;
    float acc[2][4][4];
    #pragma unroll
    for (int mt = 0; mt < 2; mt++)
        #pragma unroll
        for (int nt = 0; nt < 4; nt++)
            #pragma unroll
            for (int i = 0; i < 4; i++) acc[mt][nt][i] = 0.f;
    float rsum[8];
    #pragma unroll
    for (int i = 0; i < 8; i++) rsum[i] = 0.f;

    for (int it = 0; it < KT; it++) {
        int kb = (k0t + it) * 32;
        if (tid < 32 * DEPTH)
            pks[tid] = pb[(size_t)(kb + tid / DEPTH) * (Hh*DEPTH) + tid % DEPTH];
        __syncthreads();

        {
            float k0v = pks[lane*5+0], k1v = pks[lane*5+1], k2v = pks[lane*5+2],
                  k3v = pks[lane*5+3], k4v = pks[lane*5+4];
            float m0 = 1.f - k0v, m1 = 1.f - k1v, m2 = 1.f - k2v,
                  m3 = 1.f - k3v, m4 = 1.f - k4v;
            int kglob = kb + lane;
            #pragma unroll
            for (int jr = 0; jr < 8; jr++) {
                int row = warp * 8 + jr;
                const float* pq = pqs + row * 5;
                float p0 = pq[0], p1 = pq[1], p2 = pq[2], p3 = pq[3], p4 = pq[4];
                float prod = p0 * k0v + (1.f - p0) * m0;
                float s = prod;
                prod *= p1 * k1v + (1.f - p1) * m1; s += prod;
                prod *= p2 * k2v + (1.f - p2) * m2; s += prod;
                prod *= p3 * k3v + (1.f - p3) * m3; s += prod;
                prod *= p4 * k4v + (1.f - p4) * m4; s += prod;
                float ev = 0.f;
                if (kglob <= qt * 64 + row) ev = rnaf(expap(s * 0.2f));
                rsum[jr] += ev;
                As[row * ASTRIDE + lane] = ev;
            }
        }

        asm volatile("cp.async.wait_group 1;" ::: "memory");
        __syncthreads();

        int pf = it + 2;
        if (pf < KT) {
            uint32_t sB = sb + AV_BS * 4 + (pf % 3) * (32*BSTRIDE*4);
            int kb2 = (k0t + pf) * 32;
            #pragma unroll
            for (int t = 0; t < 4; t++) {
                int c = tid + t * 256;
                int row = c >> 5, col = c & 31;
                cp16(sB + row * (BSTRIDE*4) + col * 16,
                     Bv + (size_t)(kb2 + row) * Dd + col * 4);
            }
        }
        asm volatile("cp.async.commit_group;" ::: "memory");

        const float* Bs = sm + AV_BS + (it % 3) * (32*BSTRIDE);
        #pragma unroll
        for (int kq = 0; kq < 32; kq += 8) {
            uint32_t af[2][4], bf[4][2];
            #pragma unroll
            for (int mt = 0; mt < 2; mt++) {
                int m = wm + mt * 16 + tg;
                af[mt][0] = __float_as_uint(As[m * ASTRIDE + kq + tk]);
                af[mt][1] = __float_as_uint(As[(m + 8) * ASTRIDE + kq + tk]);
                af[mt][2] = __float_as_uint(As[m * ASTRIDE + kq + tk + 4]);
                af[mt][3] = __float_as_uint(As[(m + 8) * ASTRIDE + kq + tk + 4]);
            }
            #pragma unroll
            for (int nt = 0; nt < 4; nt++) {
                int n = wn + nt * 8 + tg;
                bf[nt][0] = __float_as_uint(Bs[(kq + tk) * BSTRIDE + n]);
                bf[nt][1] = __float_as_uint(Bs[(kq + tk + 4) * BSTRIDE + n]);
            }
            #pragma unroll
            for (int mt = 0; mt < 2; mt++)
                #pragma unroll
                for (int nt = 0; nt < 4; nt++)
                    mma_tf32(acc[mt][nt], af[mt][0], af[mt][1], af[mt][2], af[mt][3],
                             bf[nt][0], bf[nt][1]);
        }
    }

    // rowsums -> smem table
    #pragma unroll
    for (int jr = 0; jr < 8; jr++) {
        float s = rsum[jr];
        #pragma unroll
        for (int o = 16; o > 0; o >>= 1) s += __shfl_xor_sync(0xffffffffu, s, o);
        if (lane == 0) rsm[warp * 8 + jr] = s;
    }
    __syncthreads();

    if (qt < 8) {
        // self-normalized final store
        float* C = ctx + (size_t)b * Tt * Dd + h * 128;
        #pragma unroll
        for (int mt = 0; mt < 2; mt++) {
            int rl0 = wm + mt * 16 + tg;
            float i0 = 1.f / rsm[rl0], i1 = 1.f / rsm[rl0 + 8];
            #pragma unroll
            for (int nt = 0; nt < 4; nt++) {
                int r0 = qt * 64 + rl0;
                int cc = wn + nt * 8 + tk * 2;
                *(float2*)&C[(size_t)r0 * Dd + cc] =
                    make_float2(rnaf(acc[mt][nt][0] * i0), rnaf(acc[mt][nt][1] * i0));
                *(float2*)&C[(size_t)(r0 + 8) * Dd + cc] =
                    make_float2(rnaf(acc[mt][nt][2] * i1), rnaf(acc[mt][nt][3] * i1));
            }
        }
    } else {
        if (tid < 64) {
            float* rsp = rs + (size_t)ds * (Bb*Hh) * Tt + (size_t)bh * Tt + qt * 64;
            rsp[tid] = rsm[tid];
        }
        float* C = (ds ? ctx2 : ctx) + (size_t)b * Tt * Dd + h * 128;
        #pragma unroll
        for (int mt = 0; mt < 2; mt++) {
            #pragma unroll
            for (int nt = 0; nt < 4; nt++) {
                int r0 = qt * 64 + wm + mt * 16 + tg;
                int cc = wn + nt * 8 + tk * 2;
                *(float2*)&C[(size_t)r0 * Dd + cc]       = make_float2(acc[mt][nt][0], acc[mt][nt][1]);
                *(float2*)&C[(size_t)(r0 + 8) * Dd + cc] = make_float2(acc[mt][nt][2], acc[mt][nt][3]);
            }
        }
    }
}

// normalize + combine rows t>=512 only: ctx = rna((c1+c2)/(r1+r2))
__global__ __launch_bounds__(256) void ctx_norm(float4* __restrict__ ctx,
                                                const float4* __restrict__ ctx2,
                                                const float* __restrict__ rs) {
    int i = blockIdx.x * 256 + threadIdx.x;
    const int per_b = 512 * Dd / 4;
    if (i < Bb * per_b) {
        int b = i / per_b;
        int off = i - b * per_b;
        int t = 512 + off / (Dd / 4);
        int c4 = off % (Dd / 4);
        int bh = b * 8 + (c4 >> 5);
        size_t gi = (size_t)b * Tt * (Dd/4) + (size_t)t * (Dd/4) + c4;
        float denom = rs[(size_t)bh * Tt + t] + rs[(size_t)(Bb*Hh) * Tt + (size_t)bh * Tt + t];
        float inv = 1.f / denom;
        float4 xa = ctx[gi], xb = ctx2[gi];
        ctx[gi] = make_float4(rnaf((xa.x + xb.x) * inv), rnaf((xa.y + xb.y) * inv),
                              rnaf((xa.z + xb.z) * inv), rnaf((xa.w + xb.w) * inv));
    }
}

// ---------------------------------------------------------------------------
// paths GEMM split-K x4 (split-tf32) + sigmoid combine
// ---------------------------------------------------------------------------
#define PSTAGEF (2*64*36 + 2*32*136)
#define SMEM_PATHS (2*PSTAGEF*4)

__device__ __forceinline__ void paths_load(uint32_t sb, int s,
                                           const float* xh, const float* xl, int bm,
                                           const float* wh, const float* wl,
                                           int tid, int kt) {
    uint32_t base = sb + s * (PSTAGEF * 4);
    uint32_t xh_o = base;
    uint32_t xl_o = base + 64*36*4;
    uint32_t wh_o = xl_o + 64*36*4;
    uint32_t wl_o = wh_o + 32*136*4;
    int k0 = kt * 32;
    #pragma unroll
    for (int t = 0; t < 2; t++) {
        int c = tid + t * 256;
        int row = c >> 3, col = c & 7;
        size_t go = (size_t)(bm + row) * Dd + k0 + col * 4;
        uint32_t so = row * (36*4) + col * 16;
        cp16(xh_o + so, xh + go);
        cp16(xl_o + so, xl + go);
    }
    #pragma unroll
    for (int t = 0; t < 4; t++) {
        int c = tid + t * 256;
        int row = c >> 5, col = c & 31;
        size_t go = (size_t)(k0 + row) * 128 + col * 4;
        uint32_t so = row * (136*4) + col * 16;
        cp16(wh_o + so, wh + go);
        cp16(wl_o + so, wl + go);
    }
}

__global__ __launch_bounds__(256) void paths_gemm(const float* __restrict__ xh0,
                                                  const float* __restrict__ xl0,
                                                  const float* __restrict__ wh0,
                                                  const float* __restrict__ wl0,
                                                  float* __restrict__ pp) {
    extern __shared__ float sm[];
    uint32_t sb = smem_u32(sm);
    int tid = threadIdx.x;
    int warp = tid >> 5, lane = tid & 31;
    int wm = (warp & 1) * 32;
    int wn = (warp >> 1) * 32;
    int tg = lane >> 2, tk = lane & 3;
    int bm = blockIdx.x * 64;
    int sp = blockIdx.y;
    const float* xh = xh0 + sp * 256;
    const float* xl = xl0 + sp * 256;
    const float* wh = wh0 + (size_t)(sp * 256) * 128;
    const float* wl = wl0 + (size_t)(sp * 256) * 128;
    float* out = pp + (size_t)sp * NTOK * 128;
    const int KT = 8;

    float acc[2][4][4];
    #pragma unroll
    for (int mt = 0; mt < 2; mt++)
        #pragma unroll
        for (int nt = 0; nt < 4; nt++)
            #pragma unroll
            for (int i = 0; i < 4; i++) acc[mt][nt][i] = 0.f;

    paths_load(sb, 0, xh, xl, bm, wh, wl, tid, 0);
    asm volatile("cp.async.commit_group;" ::: "memory");

    for (int it = 0; it < KT; it++) {
        int pf = it + 1;
        if (pf < KT) {
            paths_load(sb, pf & 1, xh, xl, bm, wh, wl, tid, pf);
            asm volatile("cp.async.commit_group;" ::: "memory");
            asm volatile("cp.async.wait_group 1;" ::: "memory");
        } else {
            asm volatile("cp.async.wait_group 0;" ::: "memory");
        }
        __syncthreads();

        const float* Xh = sm + (it & 1) * PSTAGEF;
        const float* Xl = Xh + 64*36;
        const float* Wh = Xl + 64*36;
        const float* Wl = Wh + 32*136;
        #pragma unroll
        for (int kq = 0; kq < 32; kq += 8) {
            uint32_t ah[2][4], al[2][4], bh[4][2], bl[4][2];
            #pragma unroll
            for (int mt = 0; mt < 2; mt++) {
                int m = wm + mt * 16 + tg;
                ah[mt][0] = __float_as_uint(Xh[m * 36 + kq + tk]);
                ah[mt][1] = __float_as_uint(Xh[(m + 8) * 36 + kq + tk]);
                ah[mt][2] = __float_as_uint(Xh[m * 36 + kq + tk + 4]);
                ah[mt][3] = __float_as_uint(Xh[(m + 8) * 36 + kq + tk + 4]);
                al[mt][0] = __float_as_uint(Xl[m * 36 + kq + tk]);
                al[mt][1] = __float_as_uint(Xl[(m + 8) * 36 + kq + tk]);
                al[mt][2] = __float_as_uint(Xl[m * 36 + kq + tk + 4]);
                al[mt][3] = __float_as_uint(Xl[(m + 8) * 36 + kq + tk + 4]);
            }
            #pragma unroll
            for (int nt = 0; nt < 4; nt++) {
                int n = wn + nt * 8 + tg;
                bh[nt][0] = __float_as_uint(Wh[(kq + tk) * 136 + n]);
                bh[nt][1] = __float_as_uint(Wh[(kq + tk + 4) * 136 + n]);
                bl[nt][0] = __float_as_uint(Wl[(kq + tk) * 136 + n]);
                bl[nt][1] = __float_as_uint(Wl[(kq + tk + 4) * 136 + n]);
            }
            #pragma unroll
            for (int mt = 0; mt < 2; mt++)
                #pragma unroll
                for (int nt = 0; nt < 4; nt++) {
                    mma_tf32(acc[mt][nt], ah[mt][0], ah[mt][1], ah[mt][2], ah[mt][3],
                             bh[nt][0], bh[nt][1]);
                    mma_tf32(acc[mt][nt], ah[mt][0], ah[mt][1], ah[mt][2], ah[mt][3],
                             bl[nt][0], bl[nt][1]);
                    mma_tf32(acc[mt][nt], al[mt][0], al[mt][1], al[mt][2], al[mt][3],
                             bh[nt][0], bh[nt][1]);
                }
        }
        __syncthreads();
    }

    #pragma unroll
    for (int mt = 0; mt < 2; mt++) {
        #pragma unroll
        for (int nt = 0; nt < 4; nt++) {
            int cc = wn + nt * 8 + tk * 2;
            if (cc < Hh * DEPTH) {
                int r0 = bm + wm + mt * 16 + tg;
                out[(size_t)r0 * 128 + cc]           = acc[mt][nt][0];
                out[(size_t)r0 * 128 + cc + 1]       = acc[mt][nt][1];
                out[(size_t)(r0 + 8) * 128 + cc]     = acc[mt][nt][2];
                out[(size_t)(r0 + 8) * 128 + cc + 1] = acc[mt][nt][3];
            }
        }
    }
}

__global__ __launch_bounds__(256) void sigmoid_comb(const float* __restrict__ pp,
                                                    const float* __restrict__ bp,
                                                    float* __restrict__ paths) {
    int tok = blockIdx.x * 4 + (threadIdx.x >> 6);
    int c = threadIdx.x & 63;
    if (c < Hh * DEPTH) {
        float z = bp[c];
        #pragma unroll
        for (int s = 0; s < 4; s++)
            z += pp[(size_t)s * NTOK * 128 + (size_t)tok * 128 + c];
        paths[(size_t)tok * (Hh*DEPTH) + c] = 1.f / (1.f + expf(-z));
    }
}

// ---------------- merged staging: x split + Wv/Wo round + Wp pad ------------
__global__ __launch_bounds__(256) void prep_all(const float4* __restrict__ x,
                                                float4* __restrict__ xh,
                                                float4* __restrict__ xl,
                                                const float4* __restrict__ Wv,
                                                float4* __restrict__ wvr,
                                                const float4* __restrict__ Wo,
                                                float4* __restrict__ wor,
                                                const float* __restrict__ Wp) {
    int i = blockIdx.x * 256 + threadIdx.x;
    if (i < NTOK*Dd/4) {
        float4 v = x[i];
        float4 h = make_float4(rnaf(v.x), rnaf(v.y), rnaf(v.z), rnaf(v.w));
        xh[i] = h;
        xl[i] = make_float4(rnaf(v.x - h.x), rnaf(v.y - h.y), rnaf(v.z - h.z), rnaf(v.w - h.w));
    }
    if (i < Dd*Dd/4) {
        float4 a = Wv[i], b = Wo[i];
        wvr[i] = make_float4(rnaf(a.x), rnaf(a.y), rnaf(a.z), rnaf(a.w));
        wor[i] = make_float4(rnaf(b.x), rnaf(b.y), rnaf(b.z), rnaf(b.w));
    }
    if (i < Dd*128) {
        int k = i >> 7, n = i & 127;
        float h = 0.f, l = 0.f;
        if (n < Hh * DEPTH) {
            float w = Wp[(size_t)k * (Hh * DEPTH) + n];
            h = rnaf(w);
            l = rnaf(w - h);
        }
        g_wph[i] = h;
        g_wpl[i] = l;
    }
}

// ---------------------------------------------------------------------------
extern "C" void kernel_launch(void* const* d_in, const int* in_sizes, int n_in,
                              void* d_out, int out_size) {
    const float* x  = (const float*)d_in[0];
    const float* Wp = (const float*)d_in[1];
    const float* bp = (const float*)d_in[2];
    const float* Wv = (const float*)d_in[3];
    const float* Wo = (const float*)d_in[4];
    float* out = (float*)d_out;

    float *paths, *xr, *xlo, *wph, *wpl, *pp, *wvr, *wor, *v, *ctx, *ctx2, *rs;
    cudaGetSymbolAddress((void**)&paths, g_paths);
    cudaGetSymbolAddress((void**)&xr,    g_xr);
    cudaGetSymbolAddress((void**)&xlo,   g_xlo);
    cudaGetSymbolAddress((void**)&wph,   g_wph);
    cudaGetSymbolAddress((void**)&wpl,   g_wpl);
    cudaGetSymbolAddress((void**)&pp,    g_pp);
    cudaGetSymbolAddress((void**)&wvr,   g_wvr);
    cudaGetSymbolAddress((void**)&wor,   g_wor);
    cudaGetSymbolAddress((void**)&v,     g_v);
    cudaGetSymbolAddress((void**)&ctx,   g_ctx);
    cudaGetSymbolAddress((void**)&ctx2,  g_ctx2);
    cudaGetSymbolAddress((void**)&rs,    g_rs);

    cudaFuncSetAttribute(gemm128,    cudaFuncAttributeMaxDynamicSharedMemorySize, SMEM_GEMM2);
    cudaFuncSetAttribute(av_fused,   cudaFuncAttributeMaxDynamicSharedMemorySize, SMEM_AV);
    cudaFuncSetAttribute(paths_gemm, cudaFuncAttributeMaxDynamicSharedMemorySize, SMEM_PATHS);

    // merged staging
    prep_all<<<(NTOK*Dd/4 + 255)/256, 256>>>((const float4*)x, (float4*)xr, (float4*)xlo,
                                             (const float4*)Wv, (float4*)wvr,
                                             (const float4*)Wo, (float4*)wor, Wp);

    // paths = sigmoid(x @ Wp + bp)
    paths_gemm<<<dim3(NTOK/64, 4), 256, SMEM_PATHS>>>(xr, xlo, wph, wpl, pp);
    sigmoid_comb<<<NTOK/4, 256>>>(pp, bp, paths);

    // V = x @ Wv (rounded store)
    gemm128<<<dim3(Dd/128, NTOK/128), 256, SMEM_GEMM2>>>(xr, wvr, v, Dd, Dd, 1);

    // fused sim+softmax+attn@V
    av_fused<<<dim3(24, Bb*Hh), 256, SMEM_AV>>>(paths, v, ctx, ctx2, rs);

    // combine split rows (t >= 512)
    ctx_norm<<<(Bb*512*Dd/4 + 255)/256, 256>>>((float4*)ctx, (const float4*)ctx2, rs);

    // out = ctx @ Wo
    gemm128<<<dim3(Dd/128, NTOK/128), 256, SMEM_GEMM2>>>(ctx, wor, out, Dd, Dd, 0);
}